// round 1
// baseline (speedup 1.0000x reference)
#include <cuda_runtime.h>
#include <math.h>

// Problem constants
#define B_  4
#define S_  1024
#define D_  1024
#define H_  16
#define DKH_ 32
#define DV_  64
#define HALF_ 512

// Scratch (device globals; no allocations allowed)
__device__ float g_Q1[B_*H_*S_*DKH_];   // 2M floats
__device__ float g_K1[B_*H_*S_*DKH_];   // 2M floats
__device__ float g_V [B_*H_*S_*DV_];    // 4M floats
__device__ float g_qkv[B_*S_*H_*DV_];   // 4M floats
__device__ float g_tmp[B_*S_*D_];       // 4M floats (fc + residual, pre-LN)

// ---------------------------------------------------------------------------
// Generic tiled GEMM: C(4096 x 512) = A_slice(4096 x 512) @ W(512 x 512)
// BM=64, BN=64, BK=32, 256 threads, 4x4 micro-tile.
// mode: 0=Q1, 1=K1, 2=V1, 3=V2, 4=FC half0 (+res), 5=FC half1 (+res)
// ---------------------------------------------------------------------------
__global__ void gemm_kernel(const float* __restrict__ inQ,
                            const float* __restrict__ inK,
                            const float* __restrict__ inV,
                            const float* __restrict__ W0,
                            const float* __restrict__ W1,
                            const float* __restrict__ W2,
                            const float* __restrict__ W3,
                            int mode_base)
{
    __shared__ float As[32][65];   // [k][m], transposed store
    __shared__ float Ws[32][68];   // [k][n], padded for aligned float4 stores

    const int mode = mode_base + blockIdx.z;
    const float* W = (blockIdx.z == 0) ? W0 : (blockIdx.z == 1) ? W1
                   : (blockIdx.z == 2) ? W2 : W3;
    const float* A;
    int aoff;
    switch (mode) {
        case 0: A = inQ;   aoff = 0;    break;  // Q1 = Xq[:, :512] @ WQ1
        case 1: A = inK;   aoff = 0;    break;  // K1
        case 2: A = inV;   aoff = 0;    break;  // V1
        case 3: A = inV;   aoff = 512;  break;  // V2
        case 4: A = g_qkv; aoff = 0;    break;  // FC1
        default:A = g_qkv; aoff = 512;  break;  // FC2
    }

    const int m0 = blockIdx.x * 64;
    const int n0 = blockIdx.y * 64;
    const int tid = threadIdx.x;
    const int tx = tid & 15, ty = tid >> 4;

    float acc[4][4] = {};

    for (int k0 = 0; k0 < 512; k0 += 32) {
        // A tile 64x32 -> As[k][m]
        #pragma unroll
        for (int it = 0; it < 2; it++) {
            int f = tid + it * 256;            // 512 float4 total
            int row = f >> 3;                  // 8 float4 per row
            int c4  = (f & 7) * 4;
            float4 v = *(const float4*)&A[(size_t)(m0 + row) * 1024 + aoff + k0 + c4];
            As[c4 + 0][row] = v.x;
            As[c4 + 1][row] = v.y;
            As[c4 + 2][row] = v.z;
            As[c4 + 3][row] = v.w;
        }
        // W tile 32x64 -> Ws[k][n]
        #pragma unroll
        for (int it = 0; it < 2; it++) {
            int f = tid + it * 256;
            int kr = f >> 4;                   // 16 float4 per row
            int c4 = (f & 15) * 4;
            *(float4*)&Ws[kr][c4] = *(const float4*)&W[(size_t)(k0 + kr) * 512 + n0 + c4];
        }
        __syncthreads();

        #pragma unroll
        for (int kk = 0; kk < 32; kk++) {
            float a[4], b[4];
            #pragma unroll
            for (int i = 0; i < 4; i++) a[i] = As[kk][ty * 4 + i];
            #pragma unroll
            for (int j = 0; j < 4; j++) b[j] = Ws[kk][tx * 4 + j];
            #pragma unroll
            for (int i = 0; i < 4; i++)
                #pragma unroll
                for (int j = 0; j < 4; j++)
                    acc[i][j] = fmaf(a[i], b[j], acc[i][j]);
        }
        __syncthreads();
    }

    // Epilogue
    #pragma unroll
    for (int i = 0; i < 4; i++) {
        int row = m0 + ty * 4 + i;             // b*S + s
        int b = row >> 10, s = row & 1023;
        #pragma unroll
        for (int j = 0; j < 4; j++) {
            int col = n0 + tx * 4 + j;
            float v = acc[i][j];
            if (mode <= 1) {
                int h = col >> 5, d = col & 31;
                float* dst = (mode == 0) ? g_Q1 : g_K1;
                dst[(((size_t)(b * H_ + h)) * S_ + s) * DKH_ + d] = v;
            } else if (mode <= 3) {
                int h = col >> 5, d = col & 31;
                g_V[(((size_t)(b * H_ + h)) * S_ + s) * DV_ + (mode == 3 ? 32 : 0) + d] = v;
            } else {
                int half = mode - 4;
                size_t idx = (size_t)row * 1024 + half * 512 + col;
                g_tmp[idx] = v + inQ[idx];     // residual = input_Q same slice
            }
        }
    }
}

// ---------------------------------------------------------------------------
// Attention: one block per (b*H+h, q-tile of 64).
// Pass 1: streaming row max / sumexp. Pass 2: recompute scores, write softmax
// probs to Pout, accumulate O = P @ V. Zero-fill causal upper triangle.
// ---------------------------------------------------------------------------
struct AttnSmem {
    float Qs[64][33];   // [q][d], scaled by 1/sqrt(32)
    float Ks[64][33];   // [k][d]
    float Vs[64][65];   // [k][dv]
    float Ps[64][65];   // [q][k]
};

__global__ void attn_kernel(float* __restrict__ Pout)
{
    extern __shared__ unsigned char smem_bytes[];
    AttnSmem& sm = *reinterpret_cast<AttnSmem*>(smem_bytes);

    const int bh = blockIdx.x;     // 0..63  (b*16 + h)
    const int qt = blockIdx.y;     // 0..15
    const float* Qp = g_Q1 + (size_t)bh * S_ * DKH_ + (size_t)qt * 64 * DKH_;
    const float* Kp = g_K1 + (size_t)bh * S_ * DKH_;
    const float* Vp = g_V  + (size_t)bh * S_ * DV_;
    float* Prow = Pout + (size_t)bh * S_ * S_ + (size_t)qt * 64 * S_;

    const int tid = threadIdx.x;
    const int tx = tid & 15, ty = tid >> 4;
    const float scale = 0.17677669529663688f;  // 1/sqrt(32)

    // Load Q tile (64x32), pre-scaled
    #pragma unroll
    for (int it = 0; it < 2; it++) {
        int f = tid + it * 256;
        int row = f >> 3;
        int c4 = (f & 7) * 4;
        float4 v = *(const float4*)&Qp[row * 32 + c4];
        sm.Qs[row][c4 + 0] = v.x * scale;
        sm.Qs[row][c4 + 1] = v.y * scale;
        sm.Qs[row][c4 + 2] = v.z * scale;
        sm.Qs[row][c4 + 3] = v.w * scale;
    }

    // -------- Pass 1: row max + sumexp --------
    float mrun[4], lrun[4];
    #pragma unroll
    for (int i = 0; i < 4; i++) { mrun[i] = -1e30f; lrun[i] = 0.f; }

    for (int kt = 0; kt <= qt; kt++) {
        __syncthreads();
        #pragma unroll
        for (int it = 0; it < 2; it++) {
            int f = tid + it * 256;
            int row = f >> 3;
            int c4 = (f & 7) * 4;
            float4 v = *(const float4*)&Kp[(kt * 64 + row) * 32 + c4];
            sm.Ks[row][c4 + 0] = v.x;
            sm.Ks[row][c4 + 1] = v.y;
            sm.Ks[row][c4 + 2] = v.z;
            sm.Ks[row][c4 + 3] = v.w;
        }
        __syncthreads();

        float sacc[4][4] = {};
        #pragma unroll
        for (int d = 0; d < 32; d++) {
            float a[4], b[4];
            #pragma unroll
            for (int i = 0; i < 4; i++) a[i] = sm.Qs[ty * 4 + i][d];
            #pragma unroll
            for (int j = 0; j < 4; j++) b[j] = sm.Ks[tx * 4 + j][d];
            #pragma unroll
            for (int i = 0; i < 4; i++)
                #pragma unroll
                for (int j = 0; j < 4; j++)
                    sacc[i][j] = fmaf(a[i], b[j], sacc[i][j]);
        }
        if (kt == qt) {
            #pragma unroll
            for (int i = 0; i < 4; i++)
                #pragma unroll
                for (int j = 0; j < 4; j++)
                    if (tx * 4 + j > ty * 4 + i) sacc[i][j] = -1e30f;
        }
        #pragma unroll
        for (int i = 0; i < 4; i++) {
            float mt = fmaxf(fmaxf(sacc[i][0], sacc[i][1]), fmaxf(sacc[i][2], sacc[i][3]));
            float mn = fmaxf(mrun[i], mt);
            float ssum = __expf(sacc[i][0] - mn) + __expf(sacc[i][1] - mn)
                       + __expf(sacc[i][2] - mn) + __expf(sacc[i][3] - mn);
            lrun[i] = lrun[i] * __expf(mrun[i] - mn) + ssum;
            mrun[i] = mn;
        }
    }

    // Butterfly-reduce (m,l) across the 16 lanes sharing this row group
    #pragma unroll
    for (int off = 8; off > 0; off >>= 1) {
        #pragma unroll
        for (int i = 0; i < 4; i++) {
            float mo = __shfl_xor_sync(0xffffffffu, mrun[i], off, 16);
            float lo = __shfl_xor_sync(0xffffffffu, lrun[i], off, 16);
            float mn = fmaxf(mrun[i], mo);
            lrun[i] = lrun[i] * __expf(mrun[i] - mn) + lo * __expf(mo - mn);
            mrun[i] = mn;
        }
    }
    float linv[4];
    #pragma unroll
    for (int i = 0; i < 4; i++) linv[i] = 1.0f / lrun[i];

    // -------- Pass 2: probs + P@V --------
    float oacc[4][4] = {};

    for (int kt = 0; kt <= qt; kt++) {
        __syncthreads();
        // K tile
        #pragma unroll
        for (int it = 0; it < 2; it++) {
            int f = tid + it * 256;
            int row = f >> 3;
            int c4 = (f & 7) * 4;
            float4 v = *(const float4*)&Kp[(kt * 64 + row) * 32 + c4];
            sm.Ks[row][c4 + 0] = v.x;
            sm.Ks[row][c4 + 1] = v.y;
            sm.Ks[row][c4 + 2] = v.z;
            sm.Ks[row][c4 + 3] = v.w;
        }
        // V tile 64x64
        #pragma unroll
        for (int it = 0; it < 4; it++) {
            int f = tid + it * 256;
            int row = f >> 4;
            int c4 = (f & 15) * 4;
            float4 v = *(const float4*)&Vp[(kt * 64 + row) * 64 + c4];
            sm.Vs[row][c4 + 0] = v.x;
            sm.Vs[row][c4 + 1] = v.y;
            sm.Vs[row][c4 + 2] = v.z;
            sm.Vs[row][c4 + 3] = v.w;
        }
        __syncthreads();

        float sacc[4][4] = {};
        #pragma unroll
        for (int d = 0; d < 32; d++) {
            float a[4], b[4];
            #pragma unroll
            for (int i = 0; i < 4; i++) a[i] = sm.Qs[ty * 4 + i][d];
            #pragma unroll
            for (int j = 0; j < 4; j++) b[j] = sm.Ks[tx * 4 + j][d];
            #pragma unroll
            for (int i = 0; i < 4; i++)
                #pragma unroll
                for (int j = 0; j < 4; j++)
                    sacc[i][j] = fmaf(a[i], b[j], sacc[i][j]);
        }

        #pragma unroll
        for (int i = 0; i < 4; i++) {
            float4 pq;
            float p[4];
            #pragma unroll
            for (int j = 0; j < 4; j++) {
                bool masked = (kt == qt) && (tx * 4 + j > ty * 4 + i);
                p[j] = masked ? 0.f : __expf(sacc[i][j] - mrun[i]) * linv[i];
                sm.Ps[ty * 4 + i][tx * 4 + j] = p[j];
            }
            pq.x = p[0]; pq.y = p[1]; pq.z = p[2]; pq.w = p[3];
            *(float4*)&Prow[(size_t)(ty * 4 + i) * S_ + kt * 64 + tx * 4] = pq;
        }
        __syncthreads();

        // O += P @ V
        #pragma unroll
        for (int c = 0; c < 64; c++) {
            float pp[4], vv[4];
            #pragma unroll
            for (int i = 0; i < 4; i++) pp[i] = sm.Ps[ty * 4 + i][c];
            #pragma unroll
            for (int j = 0; j < 4; j++) vv[j] = sm.Vs[c][tx * 4 + j];
            #pragma unroll
            for (int i = 0; i < 4; i++)
                #pragma unroll
                for (int j = 0; j < 4; j++)
                    oacc[i][j] = fmaf(pp[i], vv[j], oacc[i][j]);
        }
    }

    // Zero-fill masked upper-triangle tiles
    float4 z4 = make_float4(0.f, 0.f, 0.f, 0.f);
    for (int kt = qt + 1; kt < 16; kt++) {
        #pragma unroll
        for (int i = 0; i < 4; i++)
            *(float4*)&Prow[(size_t)(ty * 4 + i) * S_ + kt * 64 + tx * 4] = z4;
    }

    // Write O into qkv_out layout (B, S, H*DV)
    const int b = bh >> 4, h = bh & 15;
    #pragma unroll
    for (int i = 0; i < 4; i++) {
        int q = qt * 64 + ty * 4 + i;
        float4 o4 = make_float4(oacc[i][0], oacc[i][1], oacc[i][2], oacc[i][3]);
        *(float4*)&g_qkv[((size_t)(b * S_ + q)) * 1024 + h * 64 + tx * 4] = o4;
    }
}

// ---------------------------------------------------------------------------
// LayerNorm over each 512-wide half of g_tmp; writes final output.
// One block per (row, half). 256 threads, 2 elements each.
// ---------------------------------------------------------------------------
__global__ void ln_kernel(const float* __restrict__ gamma,
                          const float* __restrict__ beta,
                          float* __restrict__ out)
{
    const int row = blockIdx.x >> 1;
    const int half = blockIdx.x & 1;
    const float* x = g_tmp + (size_t)row * 1024 + half * 512;
    const int tid = threadIdx.x;

    float v0 = x[tid], v1 = x[tid + 256];
    float s = v0 + v1;
    float sq = v0 * v0 + v1 * v1;
    #pragma unroll
    for (int off = 16; off > 0; off >>= 1) {
        s  += __shfl_xor_sync(0xffffffffu, s,  off);
        sq += __shfl_xor_sync(0xffffffffu, sq, off);
    }
    __shared__ float ss[8], sqq[8];
    if ((tid & 31) == 0) { ss[tid >> 5] = s; sqq[tid >> 5] = sq; }
    __syncthreads();
    float tot = 0.f, totq = 0.f;
    #pragma unroll
    for (int w = 0; w < 8; w++) { tot += ss[w]; totq += sqq[w]; }

    float mu = tot * (1.0f / 512.0f);
    float var = totq * (1.0f / 512.0f) - mu * mu;
    float rstd = rsqrtf(var + 1e-5f);

    size_t obase = (size_t)row * 1024 + half * 512;
    out[obase + tid]       = (v0 - mu) * rstd * gamma[tid]       + beta[tid];
    out[obase + tid + 256] = (v1 - mu) * rstd * gamma[tid + 256] + beta[tid + 256];
}

// ---------------------------------------------------------------------------
extern "C" void kernel_launch(void* const* d_in, const int* in_sizes, int n_in,
                              void* d_out, int out_size)
{
    const float* inQ  = (const float*)d_in[0];
    const float* inK  = (const float*)d_in[1];
    const float* inV  = (const float*)d_in[2];
    // d_in[3] = attn_mask: causal, recomputed analytically — not read.
    const float* WQ1  = (const float*)d_in[4];
    const float* WK1  = (const float*)d_in[5];
    const float* WV1  = (const float*)d_in[6];
    // d_in[7] = WQ2, d_in[8] = WK2: dead in the reference (Q2/K2 unused).
    const float* WV2  = (const float*)d_in[9];
    const float* Wfc1 = (const float*)d_in[10];
    const float* Wfc2 = (const float*)d_in[11];
    const float* ln_g = (const float*)d_in[12];
    const float* ln_b = (const float*)d_in[13];

    float* out  = (float*)d_out;
    float* Pout = out + (size_t)B_ * S_ * D_;   // softmax_attn region

    cudaFuncSetAttribute(attn_kernel, cudaFuncAttributeMaxDynamicSharedMemorySize,
                         (int)sizeof(AttnSmem));

    dim3 blk(256);
    // Projections: Q1, K1, V1, V2
    gemm_kernel<<<dim3(64, 8, 4), blk>>>(inQ, inK, inV, WQ1, WK1, WV1, WV2, 0);
    // Attention + softmax_attn output + P@V
    attn_kernel<<<dim3(64, 16), blk, sizeof(AttnSmem)>>>(Pout);
    // FC + residual
    gemm_kernel<<<dim3(64, 8, 2), blk>>>(inQ, inK, inV, Wfc1, Wfc2, Wfc1, Wfc2, 4);
    // LayerNorm -> final output
    ln_kernel<<<dim3(B_ * S_ * 2), blk>>>(ln_g, ln_b, out);
}

// round 3
// speedup vs baseline: 1.2866x; 1.2866x over previous
#include <cuda_runtime.h>
#include <cuda_bf16.h>
#include <math.h>
#include <stdint.h>

// Problem constants
#define B_  4
#define S_  1024
#define D_  1024
#define H_  16
#define DKH_ 32
#define DV_  64
#define HALF_ 512

// Scratch (device globals; no allocations allowed)
__device__ float g_Q1[B_*H_*S_*DKH_];
__device__ float g_K1[B_*H_*S_*DKH_];
__device__ float g_V [B_*H_*S_*DV_];
__device__ float g_qkv[B_*S_*H_*DV_];
__device__ float g_tmp[B_*S_*D_];

// ===========================================================================
// warp-mma helpers (baseline PTX, works on plain sm_103 target)
// ===========================================================================
__device__ __forceinline__ uint32_t smem_u32(const void* p) {
    uint32_t a;
    asm("{ .reg .u64 t; cvta.to.shared.u64 t, %1; cvt.u32.u64 %0, t; }"
        : "=r"(a) : "l"(p));
    return a;
}
__device__ __forceinline__ void ldsm_x4(uint32_t& r0, uint32_t& r1,
                                        uint32_t& r2, uint32_t& r3, uint32_t addr) {
    asm volatile("ldmatrix.sync.aligned.m8n8.x4.shared.b16 {%0,%1,%2,%3}, [%4];"
                 : "=r"(r0), "=r"(r1), "=r"(r2), "=r"(r3) : "r"(addr));
}
__device__ __forceinline__ void ldsm_x2t(uint32_t& r0, uint32_t& r1, uint32_t addr) {
    asm volatile("ldmatrix.sync.aligned.m8n8.x2.trans.shared.b16 {%0,%1}, [%2];"
                 : "=r"(r0), "=r"(r1) : "r"(addr));
}
__device__ __forceinline__ void mma_bf16(float* c, uint32_t a0, uint32_t a1,
                                         uint32_t a2, uint32_t a3,
                                         uint32_t b0, uint32_t b1) {
    asm volatile("mma.sync.aligned.m16n8k16.row.col.f32.bf16.bf16.f32 "
                 "{%0,%1,%2,%3}, {%4,%5,%6,%7}, {%8,%9}, {%0,%1,%2,%3};"
                 : "+f"(c[0]), "+f"(c[1]), "+f"(c[2]), "+f"(c[3])
                 : "r"(a0), "r"(a1), "r"(a2), "r"(a3), "r"(b0), "r"(b1));
}
__device__ __forceinline__ uint32_t pack_bf16(__nv_bfloat16 a, __nv_bfloat16 b) {
    __nv_bfloat162 t; t.x = a; t.y = b;
    return *reinterpret_cast<uint32_t*>(&t);
}
// split fp32 -> (hi, lo) bf16 pair packed as uint32 for 2 consecutive values
__device__ __forceinline__ void split2(float x, float y, uint32_t& hi, uint32_t& lo) {
    __nv_bfloat16 hx = __float2bfloat16_rn(x);
    __nv_bfloat16 hy = __float2bfloat16_rn(y);
    __nv_bfloat16 lx = __float2bfloat16_rn(x - __bfloat162float(hx));
    __nv_bfloat16 ly = __float2bfloat16_rn(y - __bfloat162float(hy));
    hi = pack_bf16(hx, hy);
    lo = pack_bf16(lx, ly);
}

// ===========================================================================
// HMMA GEMM: C(4096x512) = A_slice(4096x512) @ W(512x512), bf16 split-2
// (3-term). CTA tile 128x128, 8 warps (warp tile 64x32), K chunk 32.
// mode: 0=Q1, 1=K1, 2=V1, 3=V2, 4=FC half0 (+res), 5=FC half1 (+res)
// ===========================================================================
#define APITCH 80    // bytes per A smem row (32 bf16 = 64B + 16B pad)
#define BPITCH 272   // bytes per B smem row (128 bf16 = 256B + 16B pad)

struct GSmem {
    unsigned char Ah[128 * APITCH];
    unsigned char Al[128 * APITCH];
    unsigned char Bh[32 * BPITCH];
    unsigned char Bl[32 * BPITCH];
};

__global__ void __launch_bounds__(256, 1)
mma_gemm(const float* __restrict__ inQ,
         const float* __restrict__ inK,
         const float* __restrict__ inV,
         const float* __restrict__ W0,
         const float* __restrict__ W1,
         const float* __restrict__ W2,
         const float* __restrict__ W3,
         int mode_base)
{
    __shared__ GSmem gs;

    const int mode = mode_base + blockIdx.z;
    const float* W = (blockIdx.z == 0) ? W0 : (blockIdx.z == 1) ? W1
                   : (blockIdx.z == 2) ? W2 : W3;
    const float* A;
    int aoff;
    switch (mode) {
        case 0: A = inQ;   aoff = 0;    break;
        case 1: A = inK;   aoff = 0;    break;
        case 2: A = inV;   aoff = 0;    break;
        case 3: A = inV;   aoff = 512;  break;
        case 4: A = g_qkv; aoff = 0;    break;
        default:A = g_qkv; aoff = 512;  break;
    }

    const int m0 = blockIdx.x * 128;
    const int n0 = blockIdx.y * 128;
    const int tid  = threadIdx.x;
    const int wid  = tid >> 5;
    const int lane = tid & 31;
    const int wy = wid >> 2;        // 0..1  (64 rows each)
    const int wx = wid & 3;         // 0..3  (32 cols each)

    const uint32_t ah_base = smem_u32(gs.Ah);
    const uint32_t al_base = smem_u32(gs.Al);
    const uint32_t bh_base = smem_u32(gs.Bh);
    const uint32_t bl_base = smem_u32(gs.Bl);

    float c[4][4][4] = {};   // [mt][nt][frag]

    // ldmatrix per-thread address components
    const int a_row_in_tile = lane & 15;        // 0..15
    const int a_kseg        = (lane >> 4) & 1;  // 0/1 (8-col halves)
    const int b_krow        = (lane & 7) + ((lane >> 3) & 1) * 8;  // 0..15 (lanes 0-15 valid)

    for (int k0 = 0; k0 < 512; k0 += 32) {
        // ---- fill A: 128 rows x 32 k, fp32 -> hi/lo bf16 ----
        #pragma unroll
        for (int it = 0; it < 4; ++it) {
            int idx = tid + it * 256;           // 0..1023
            int r   = idx >> 3;                 // 0..127
            int qk  = (idx & 7) * 4;            // 0..28
            float4 v = *(const float4*)&A[(size_t)(m0 + r) * 1024 + aoff + k0 + qk];
            uint32_t h0, l0, h1, l1;
            split2(v.x, v.y, h0, l0);
            split2(v.z, v.w, h1, l1);
            uint32_t off = (uint32_t)(r * APITCH + qk * 2);
            *(uint2*)(gs.Ah + off) = make_uint2(h0, h1);
            *(uint2*)(gs.Al + off) = make_uint2(l0, l1);
        }
        // ---- fill B: 32 k-rows x 128 n, [k][n] layout (coalesced) ----
        #pragma unroll
        for (int it = 0; it < 4; ++it) {
            int idx = tid + it * 256;           // 0..1023
            int kr  = idx >> 5;                 // 0..31
            int qn  = (idx & 31) * 4;           // 0..124
            float4 v = *(const float4*)&W[(size_t)(k0 + kr) * 512 + n0 + qn];
            uint32_t h0, l0, h1, l1;
            split2(v.x, v.y, h0, l0);
            split2(v.z, v.w, h1, l1);
            uint32_t off = (uint32_t)(kr * BPITCH + qn * 2);
            *(uint2*)(gs.Bh + off) = make_uint2(h0, h1);
            *(uint2*)(gs.Bl + off) = make_uint2(l0, l1);
        }
        __syncthreads();

        #pragma unroll
        for (int ks = 0; ks < 2; ++ks) {        // two k16 steps per chunk
            // A fragments (hi & lo) for this warp's 4 m16 tiles
            uint32_t ahf[4][4], alf[4][4];
            #pragma unroll
            for (int mt = 0; mt < 4; ++mt) {
                int row = wy * 64 + mt * 16 + a_row_in_tile;
                uint32_t aoffb = (uint32_t)(row * APITCH + ks * 32 + a_kseg * 16);
                ldsm_x4(ahf[mt][0], ahf[mt][1], ahf[mt][2], ahf[mt][3], ah_base + aoffb);
                ldsm_x4(alf[mt][0], alf[mt][1], alf[mt][2], alf[mt][3], al_base + aoffb);
            }
            // B fragments (hi & lo) for this warp's 4 n8 tiles
            uint32_t bhf[4][2], blf[4][2];
            #pragma unroll
            for (int nt = 0; nt < 4; ++nt) {
                uint32_t boffb = (uint32_t)((ks * 16 + b_krow) * BPITCH
                                            + (wx * 32 + nt * 8) * 2);
                ldsm_x2t(bhf[nt][0], bhf[nt][1], bh_base + boffb);
                ldsm_x2t(blf[nt][0], blf[nt][1], bl_base + boffb);
            }
            // 3-term split MMAs
            #pragma unroll
            for (int mt = 0; mt < 4; ++mt) {
                #pragma unroll
                for (int nt = 0; nt < 4; ++nt) {
                    mma_bf16(c[mt][nt], ahf[mt][0], ahf[mt][1], ahf[mt][2], ahf[mt][3],
                             bhf[nt][0], bhf[nt][1]);
                    mma_bf16(c[mt][nt], ahf[mt][0], ahf[mt][1], ahf[mt][2], ahf[mt][3],
                             blf[nt][0], blf[nt][1]);
                    mma_bf16(c[mt][nt], alf[mt][0], alf[mt][1], alf[mt][2], alf[mt][3],
                             bhf[nt][0], bhf[nt][1]);
                }
            }
        }
        __syncthreads();
    }

    // ---- epilogue ----
    const int gid = lane >> 2;     // 0..7 (row within 8)
    const int tig = lane & 3;      // 0..3 (col pair)

    #pragma unroll
    for (int mt = 0; mt < 4; ++mt) {
        int row = m0 + wy * 64 + mt * 16 + gid;
        int b = row >> 10, s = row & 1023;
        #pragma unroll
        for (int nt = 0; nt < 4; ++nt) {
            int col = n0 + wx * 32 + nt * 8 + tig * 2;
            float2 v01 = make_float2(c[mt][nt][0], c[mt][nt][1]);
            float2 v23 = make_float2(c[mt][nt][2], c[mt][nt][3]);
            if (mode <= 1) {
                int h = col >> 5, d = col & 31;
                float* dst = (mode == 0) ? g_Q1 : g_K1;
                size_t base = (((size_t)(b * H_ + h)) * S_) * DKH_ + d;
                *(float2*)&dst[base + (size_t)s * DKH_]       = v01;
                *(float2*)&dst[base + (size_t)(s + 8) * DKH_] = v23;
            } else if (mode <= 3) {
                int h = col >> 5, d = (col & 31) + (mode == 3 ? 32 : 0);
                size_t base = (((size_t)(b * H_ + h)) * S_) * DV_ + d;
                *(float2*)&g_V[base + (size_t)s * DV_]       = v01;
                *(float2*)&g_V[base + (size_t)(s + 8) * DV_] = v23;
            } else {
                int half = mode - 4;
                size_t idx0 = (size_t)row * 1024 + half * 512 + col;
                size_t idx1 = idx0 + 8 * 1024;
                float2 r0 = *(const float2*)&inQ[idx0];
                float2 r1 = *(const float2*)&inQ[idx1];
                *(float2*)&g_tmp[idx0] = make_float2(v01.x + r0.x, v01.y + r0.y);
                *(float2*)&g_tmp[idx1] = make_float2(v23.x + r1.x, v23.y + r1.y);
            }
        }
    }
}

// ---------------------------------------------------------------------------
// Attention: one block per (b*H+h, q-tile of 64).  (unchanged, proven)
// ---------------------------------------------------------------------------
struct AttnSmem {
    float Qs[64][33];
    float Ks[64][33];
    float Vs[64][65];
    float Ps[64][65];
};

__global__ void attn_kernel(float* __restrict__ Pout)
{
    extern __shared__ unsigned char smem_bytes[];
    AttnSmem& sm = *reinterpret_cast<AttnSmem*>(smem_bytes);

    const int bh = blockIdx.x;
    const int qt = blockIdx.y;
    const float* Qp = g_Q1 + (size_t)bh * S_ * DKH_ + (size_t)qt * 64 * DKH_;
    const float* Kp = g_K1 + (size_t)bh * S_ * DKH_;
    const float* Vp = g_V  + (size_t)bh * S_ * DV_;
    float* Prow = Pout + (size_t)bh * S_ * S_ + (size_t)qt * 64 * S_;

    const int tid = threadIdx.x;
    const int tx = tid & 15, ty = tid >> 4;
    const float scale = 0.17677669529663688f;

    #pragma unroll
    for (int it = 0; it < 2; it++) {
        int f = tid + it * 256;
        int row = f >> 3;
        int c4 = (f & 7) * 4;
        float4 v = *(const float4*)&Qp[row * 32 + c4];
        sm.Qs[row][c4 + 0] = v.x * scale;
        sm.Qs[row][c4 + 1] = v.y * scale;
        sm.Qs[row][c4 + 2] = v.z * scale;
        sm.Qs[row][c4 + 3] = v.w * scale;
    }

    float mrun[4], lrun[4];
    #pragma unroll
    for (int i = 0; i < 4; i++) { mrun[i] = -1e30f; lrun[i] = 0.f; }

    for (int kt = 0; kt <= qt; kt++) {
        __syncthreads();
        #pragma unroll
        for (int it = 0; it < 2; it++) {
            int f = tid + it * 256;
            int row = f >> 3;
            int c4 = (f & 7) * 4;
            float4 v = *(const float4*)&Kp[(kt * 64 + row) * 32 + c4];
            sm.Ks[row][c4 + 0] = v.x;
            sm.Ks[row][c4 + 1] = v.y;
            sm.Ks[row][c4 + 2] = v.z;
            sm.Ks[row][c4 + 3] = v.w;
        }
        __syncthreads();

        float sacc[4][4] = {};
        #pragma unroll
        for (int d = 0; d < 32; d++) {
            float a[4], b[4];
            #pragma unroll
            for (int i = 0; i < 4; i++) a[i] = sm.Qs[ty * 4 + i][d];
            #pragma unroll
            for (int j = 0; j < 4; j++) b[j] = sm.Ks[tx * 4 + j][d];
            #pragma unroll
            for (int i = 0; i < 4; i++)
                #pragma unroll
                for (int j = 0; j < 4; j++)
                    sacc[i][j] = fmaf(a[i], b[j], sacc[i][j]);
        }
        if (kt == qt) {
            #pragma unroll
            for (int i = 0; i < 4; i++)
                #pragma unroll
                for (int j = 0; j < 4; j++)
                    if (tx * 4 + j > ty * 4 + i) sacc[i][j] = -1e30f;
        }
        #pragma unroll
        for (int i = 0; i < 4; i++) {
            float mt = fmaxf(fmaxf(sacc[i][0], sacc[i][1]), fmaxf(sacc[i][2], sacc[i][3]));
            float mn = fmaxf(mrun[i], mt);
            float ssum = __expf(sacc[i][0] - mn) + __expf(sacc[i][1] - mn)
                       + __expf(sacc[i][2] - mn) + __expf(sacc[i][3] - mn);
            lrun[i] = lrun[i] * __expf(mrun[i] - mn) + ssum;
            mrun[i] = mn;
        }
    }

    #pragma unroll
    for (int off = 8; off > 0; off >>= 1) {
        #pragma unroll
        for (int i = 0; i < 4; i++) {
            float mo = __shfl_xor_sync(0xffffffffu, mrun[i], off, 16);
            float lo = __shfl_xor_sync(0xffffffffu, lrun[i], off, 16);
            float mn = fmaxf(mrun[i], mo);
            lrun[i] = lrun[i] * __expf(mrun[i] - mn) + lo * __expf(mo - mn);
            mrun[i] = mn;
        }
    }
    float linv[4];
    #pragma unroll
    for (int i = 0; i < 4; i++) linv[i] = 1.0f / lrun[i];

    float oacc[4][4] = {};

    for (int kt = 0; kt <= qt; kt++) {
        __syncthreads();
        #pragma unroll
        for (int it = 0; it < 2; it++) {
            int f = tid + it * 256;
            int row = f >> 3;
            int c4 = (f & 7) * 4;
            float4 v = *(const float4*)&Kp[(kt * 64 + row) * 32 + c4];
            sm.Ks[row][c4 + 0] = v.x;
            sm.Ks[row][c4 + 1] = v.y;
            sm.Ks[row][c4 + 2] = v.z;
            sm.Ks[row][c4 + 3] = v.w;
        }
        #pragma unroll
        for (int it = 0; it < 4; it++) {
            int f = tid + it * 256;
            int row = f >> 4;
            int c4 = (f & 15) * 4;
            float4 v = *(const float4*)&Vp[(kt * 64 + row) * 64 + c4];
            sm.Vs[row][c4 + 0] = v.x;
            sm.Vs[row][c4 + 1] = v.y;
            sm.Vs[row][c4 + 2] = v.z;
            sm.Vs[row][c4 + 3] = v.w;
        }
        __syncthreads();

        float sacc[4][4] = {};
        #pragma unroll
        for (int d = 0; d < 32; d++) {
            float a[4], b[4];
            #pragma unroll
            for (int i = 0; i < 4; i++) a[i] = sm.Qs[ty * 4 + i][d];
            #pragma unroll
            for (int j = 0; j < 4; j++) b[j] = sm.Ks[tx * 4 + j][d];
            #pragma unroll
            for (int i = 0; i < 4; i++)
                #pragma unroll
                for (int j = 0; j < 4; j++)
                    sacc[i][j] = fmaf(a[i], b[j], sacc[i][j]);
        }

        #pragma unroll
        for (int i = 0; i < 4; i++) {
            float4 pq;
            float p[4];
            #pragma unroll
            for (int j = 0; j < 4; j++) {
                bool masked = (kt == qt) && (tx * 4 + j > ty * 4 + i);
                p[j] = masked ? 0.f : __expf(sacc[i][j] - mrun[i]) * linv[i];
                sm.Ps[ty * 4 + i][tx * 4 + j] = p[j];
            }
            pq.x = p[0]; pq.y = p[1]; pq.z = p[2]; pq.w = p[3];
            *(float4*)&Prow[(size_t)(ty * 4 + i) * S_ + kt * 64 + tx * 4] = pq;
        }
        __syncthreads();

        #pragma unroll
        for (int cidx = 0; cidx < 64; cidx++) {
            float pp[4], vv[4];
            #pragma unroll
            for (int i = 0; i < 4; i++) pp[i] = sm.Ps[ty * 4 + i][cidx];
            #pragma unroll
            for (int j = 0; j < 4; j++) vv[j] = sm.Vs[cidx][tx * 4 + j];
            #pragma unroll
            for (int i = 0; i < 4; i++)
                #pragma unroll
                for (int j = 0; j < 4; j++)
                    oacc[i][j] = fmaf(pp[i], vv[j], oacc[i][j]);
        }
    }

    float4 z4 = make_float4(0.f, 0.f, 0.f, 0.f);
    for (int kt = qt + 1; kt < 16; kt++) {
        #pragma unroll
        for (int i = 0; i < 4; i++)
            *(float4*)&Prow[(size_t)(ty * 4 + i) * S_ + kt * 64 + tx * 4] = z4;
    }

    const int b = bh >> 4, h = bh & 15;
    #pragma unroll
    for (int i = 0; i < 4; i++) {
        int q = qt * 64 + ty * 4 + i;
        float4 o4 = make_float4(oacc[i][0], oacc[i][1], oacc[i][2], oacc[i][3]);
        *(float4*)&g_qkv[((size_t)(b * S_ + q)) * 1024 + h * 64 + tx * 4] = o4;
    }
}

// ---------------------------------------------------------------------------
// LayerNorm (unchanged)
// ---------------------------------------------------------------------------
__global__ void ln_kernel(const float* __restrict__ gamma,
                          const float* __restrict__ beta,
                          float* __restrict__ out)
{
    const int row = blockIdx.x >> 1;
    const int half = blockIdx.x & 1;
    const float* x = g_tmp + (size_t)row * 1024 + half * 512;
    const int tid = threadIdx.x;

    float v0 = x[tid], v1 = x[tid + 256];
    float s = v0 + v1;
    float sq = v0 * v0 + v1 * v1;
    #pragma unroll
    for (int off = 16; off > 0; off >>= 1) {
        s  += __shfl_xor_sync(0xffffffffu, s,  off);
        sq += __shfl_xor_sync(0xffffffffu, sq, off);
    }
    __shared__ float ss[8], sqq[8];
    if ((tid & 31) == 0) { ss[tid >> 5] = s; sqq[tid >> 5] = sq; }
    __syncthreads();
    float tot = 0.f, totq = 0.f;
    #pragma unroll
    for (int w = 0; w < 8; w++) { tot += ss[w]; totq += sqq[w]; }

    float mu = tot * (1.0f / 512.0f);
    float var = totq * (1.0f / 512.0f) - mu * mu;
    float rstd = rsqrtf(var + 1e-5f);

    size_t obase = (size_t)row * 1024 + half * 512;
    out[obase + tid]       = (v0 - mu) * rstd * gamma[tid]       + beta[tid];
    out[obase + tid + 256] = (v1 - mu) * rstd * gamma[tid + 256] + beta[tid + 256];
}

// ---------------------------------------------------------------------------
extern "C" void kernel_launch(void* const* d_in, const int* in_sizes, int n_in,
                              void* d_out, int out_size)
{
    const float* inQ  = (const float*)d_in[0];
    const float* inK  = (const float*)d_in[1];
    const float* inV  = (const float*)d_in[2];
    const float* WQ1  = (const float*)d_in[4];
    const float* WK1  = (const float*)d_in[5];
    const float* WV1  = (const float*)d_in[6];
    const float* WV2  = (const float*)d_in[9];
    const float* Wfc1 = (const float*)d_in[10];
    const float* Wfc2 = (const float*)d_in[11];
    const float* ln_g = (const float*)d_in[12];
    const float* ln_b = (const float*)d_in[13];

    float* out  = (float*)d_out;
    float* Pout = out + (size_t)B_ * S_ * D_;

    static int attrs_set = 0;
    if (!attrs_set) {
        cudaFuncSetAttribute(attn_kernel, cudaFuncAttributeMaxDynamicSharedMemorySize,
                             (int)sizeof(AttnSmem));
        attrs_set = 1;
    }

    // Projections: Q1, K1, V1, V2  (HMMA bf16 split-2)
    mma_gemm<<<dim3(32, 4, 4), 256>>>(inQ, inK, inV, WQ1, WK1, WV1, WV2, 0);
    // Attention + softmax_attn output + P@V
    attn_kernel<<<dim3(64, 16), 256, sizeof(AttnSmem)>>>(Pout);
    // FC + residual (HMMA)
    mma_gemm<<<dim3(32, 4, 2), 256>>>(inQ, inK, inV, Wfc1, Wfc2, Wfc1, Wfc2, 4);
    // LayerNorm -> final output
    ln_kernel<<<dim3(B_ * S_ * 2), 256>>>(ln_g, ln_b, out);
}

// round 4
// speedup vs baseline: 1.4599x; 1.1346x over previous
#include <cuda_runtime.h>
#include <cuda_bf16.h>
#include <math.h>
#include <stdint.h>

// Problem constants
#define B_  4
#define S_  1024
#define D_  1024
#define H_  16
#define DKH_ 32
#define DV_  64

// Scratch (device globals; no allocations allowed)
__device__ __nv_bfloat16 g_Q1h[64*1024*32];  // [bh][s][32] pre-scaled by 1/sqrt(32)
__device__ __nv_bfloat16 g_Q1l[64*1024*32];
__device__ __nv_bfloat16 g_K1h[64*1024*32];
__device__ __nv_bfloat16 g_K1l[64*1024*32];
__device__ __nv_bfloat16 g_Vh [64*1024*64];  // [bh][s][64]
__device__ __nv_bfloat16 g_Vl [64*1024*64];
__device__ float g_qkv[B_*S_*H_*DV_];
__device__ float g_tmp[B_*S_*D_];

// ===========================================================================
// warp-mma helpers (baseline PTX, works on plain sm_103 target)
// ===========================================================================
__device__ __forceinline__ uint32_t smem_u32(const void* p) {
    uint32_t a;
    asm("{ .reg .u64 t; cvta.to.shared.u64 t, %1; cvt.u32.u64 %0, t; }"
        : "=r"(a) : "l"(p));
    return a;
}
__device__ __forceinline__ void ldsm_x4(uint32_t& r0, uint32_t& r1,
                                        uint32_t& r2, uint32_t& r3, uint32_t addr) {
    asm volatile("ldmatrix.sync.aligned.m8n8.x4.shared.b16 {%0,%1,%2,%3}, [%4];"
                 : "=r"(r0), "=r"(r1), "=r"(r2), "=r"(r3) : "r"(addr));
}
__device__ __forceinline__ void ldsm_x2(uint32_t& r0, uint32_t& r1, uint32_t addr) {
    asm volatile("ldmatrix.sync.aligned.m8n8.x2.shared.b16 {%0,%1}, [%2];"
                 : "=r"(r0), "=r"(r1) : "r"(addr));
}
__device__ __forceinline__ void ldsm_x2t(uint32_t& r0, uint32_t& r1, uint32_t addr) {
    asm volatile("ldmatrix.sync.aligned.m8n8.x2.trans.shared.b16 {%0,%1}, [%2];"
                 : "=r"(r0), "=r"(r1) : "r"(addr));
}
__device__ __forceinline__ void mma_bf16(float* c, uint32_t a0, uint32_t a1,
                                         uint32_t a2, uint32_t a3,
                                         uint32_t b0, uint32_t b1) {
    asm volatile("mma.sync.aligned.m16n8k16.row.col.f32.bf16.bf16.f32 "
                 "{%0,%1,%2,%3}, {%4,%5,%6,%7}, {%8,%9}, {%0,%1,%2,%3};"
                 : "+f"(c[0]), "+f"(c[1]), "+f"(c[2]), "+f"(c[3])
                 : "r"(a0), "r"(a1), "r"(a2), "r"(a3), "r"(b0), "r"(b1));
}
__device__ __forceinline__ uint32_t pack_bf16(__nv_bfloat16 a, __nv_bfloat16 b) {
    __nv_bfloat162 t; t.x = a; t.y = b;
    return *reinterpret_cast<uint32_t*>(&t);
}
__device__ __forceinline__ void split2(float x, float y, uint32_t& hi, uint32_t& lo) {
    __nv_bfloat16 hx = __float2bfloat16_rn(x);
    __nv_bfloat16 hy = __float2bfloat16_rn(y);
    __nv_bfloat16 lx = __float2bfloat16_rn(x - __bfloat162float(hx));
    __nv_bfloat16 ly = __float2bfloat16_rn(y - __bfloat162float(hy));
    hi = pack_bf16(hx, hy);
    lo = pack_bf16(lx, ly);
}

// ===========================================================================
// HMMA GEMM: C(4096x512) = A_slice(4096x512) @ W(512x512), bf16 split-2.
// CTA tile 128x128, 8 warps, K chunk 32.
// mode: 0=Q1(bf16,scaled), 1=K1(bf16), 2=V1(bf16), 3=V2(bf16),
//       4=FC half0 (+res, fp32), 5=FC half1 (+res, fp32)
// ===========================================================================
#define APITCH 80
#define BPITCH 272

struct GSmem {
    unsigned char Ah[128 * APITCH];
    unsigned char Al[128 * APITCH];
    unsigned char Bh[32 * BPITCH];
    unsigned char Bl[32 * BPITCH];
};

__global__ void __launch_bounds__(256, 1)
mma_gemm(const float* __restrict__ inQ,
         const float* __restrict__ inK,
         const float* __restrict__ inV,
         const float* __restrict__ W0,
         const float* __restrict__ W1,
         const float* __restrict__ W2,
         const float* __restrict__ W3,
         int mode_base)
{
    __shared__ GSmem gs;

    const int mode = mode_base + blockIdx.z;
    const float* W = (blockIdx.z == 0) ? W0 : (blockIdx.z == 1) ? W1
                   : (blockIdx.z == 2) ? W2 : W3;
    const float* A;
    int aoff;
    switch (mode) {
        case 0: A = inQ;   aoff = 0;    break;
        case 1: A = inK;   aoff = 0;    break;
        case 2: A = inV;   aoff = 0;    break;
        case 3: A = inV;   aoff = 512;  break;
        case 4: A = g_qkv; aoff = 0;    break;
        default:A = g_qkv; aoff = 512;  break;
    }

    const int m0 = blockIdx.x * 128;
    const int n0 = blockIdx.y * 128;
    const int tid  = threadIdx.x;
    const int wid  = tid >> 5;
    const int lane = tid & 31;
    const int wy = wid >> 2;
    const int wx = wid & 3;

    const uint32_t ah_base = smem_u32(gs.Ah);
    const uint32_t al_base = smem_u32(gs.Al);
    const uint32_t bh_base = smem_u32(gs.Bh);
    const uint32_t bl_base = smem_u32(gs.Bl);

    float c[4][4][4] = {};

    const int a_row_in_tile = lane & 15;
    const int a_kseg        = (lane >> 4) & 1;
    const int b_krow        = (lane & 7) + ((lane >> 3) & 1) * 8;

    for (int k0 = 0; k0 < 512; k0 += 32) {
        #pragma unroll
        for (int it = 0; it < 4; ++it) {
            int idx = tid + it * 256;
            int r   = idx >> 3;
            int qk  = (idx & 7) * 4;
            float4 v = *(const float4*)&A[(size_t)(m0 + r) * 1024 + aoff + k0 + qk];
            uint32_t h0, l0, h1, l1;
            split2(v.x, v.y, h0, l0);
            split2(v.z, v.w, h1, l1);
            uint32_t off = (uint32_t)(r * APITCH + qk * 2);
            *(uint2*)(gs.Ah + off) = make_uint2(h0, h1);
            *(uint2*)(gs.Al + off) = make_uint2(l0, l1);
        }
        #pragma unroll
        for (int it = 0; it < 4; ++it) {
            int idx = tid + it * 256;
            int kr  = idx >> 5;
            int qn  = (idx & 31) * 4;
            float4 v = *(const float4*)&W[(size_t)(k0 + kr) * 512 + n0 + qn];
            uint32_t h0, l0, h1, l1;
            split2(v.x, v.y, h0, l0);
            split2(v.z, v.w, h1, l1);
            uint32_t off = (uint32_t)(kr * BPITCH + qn * 2);
            *(uint2*)(gs.Bh + off) = make_uint2(h0, h1);
            *(uint2*)(gs.Bl + off) = make_uint2(l0, l1);
        }
        __syncthreads();

        #pragma unroll
        for (int ks = 0; ks < 2; ++ks) {
            uint32_t ahf[4][4], alf[4][4];
            #pragma unroll
            for (int mt = 0; mt < 4; ++mt) {
                int row = wy * 64 + mt * 16 + a_row_in_tile;
                uint32_t aoffb = (uint32_t)(row * APITCH + ks * 32 + a_kseg * 16);
                ldsm_x4(ahf[mt][0], ahf[mt][1], ahf[mt][2], ahf[mt][3], ah_base + aoffb);
                ldsm_x4(alf[mt][0], alf[mt][1], alf[mt][2], alf[mt][3], al_base + aoffb);
            }
            uint32_t bhf[4][2], blf[4][2];
            #pragma unroll
            for (int nt = 0; nt < 4; ++nt) {
                uint32_t boffb = (uint32_t)((ks * 16 + b_krow) * BPITCH
                                            + (wx * 32 + nt * 8) * 2);
                ldsm_x2t(bhf[nt][0], bhf[nt][1], bh_base + boffb);
                ldsm_x2t(blf[nt][0], blf[nt][1], bl_base + boffb);
            }
            #pragma unroll
            for (int mt = 0; mt < 4; ++mt) {
                #pragma unroll
                for (int nt = 0; nt < 4; ++nt) {
                    mma_bf16(c[mt][nt], ahf[mt][0], ahf[mt][1], ahf[mt][2], ahf[mt][3],
                             bhf[nt][0], bhf[nt][1]);
                    mma_bf16(c[mt][nt], ahf[mt][0], ahf[mt][1], ahf[mt][2], ahf[mt][3],
                             blf[nt][0], blf[nt][1]);
                    mma_bf16(c[mt][nt], alf[mt][0], alf[mt][1], alf[mt][2], alf[mt][3],
                             bhf[nt][0], bhf[nt][1]);
                }
            }
        }
        __syncthreads();
    }

    const int gid = lane >> 2;
    const int tig = lane & 3;

    #pragma unroll
    for (int mt = 0; mt < 4; ++mt) {
        int row = m0 + wy * 64 + mt * 16 + gid;
        int b = row >> 10, s = row & 1023;
        #pragma unroll
        for (int nt = 0; nt < 4; ++nt) {
            int col = n0 + wx * 32 + nt * 8 + tig * 2;
            float2 v01 = make_float2(c[mt][nt][0], c[mt][nt][1]);
            float2 v23 = make_float2(c[mt][nt][2], c[mt][nt][3]);
            if (mode <= 1) {
                int h = col >> 5, d = col & 31;
                __nv_bfloat16* dh = (mode == 0) ? g_Q1h : g_K1h;
                __nv_bfloat16* dl = (mode == 0) ? g_Q1l : g_K1l;
                float sc = (mode == 0) ? 0.17677669529663688f : 1.0f;
                size_t base = ((size_t)(b * 16 + h) * 1024) * 32 + d;
                uint32_t hi, lo;
                split2(v01.x * sc, v01.y * sc, hi, lo);
                *(uint32_t*)&dh[base + (size_t)s * 32] = hi;
                *(uint32_t*)&dl[base + (size_t)s * 32] = lo;
                split2(v23.x * sc, v23.y * sc, hi, lo);
                *(uint32_t*)&dh[base + (size_t)(s + 8) * 32] = hi;
                *(uint32_t*)&dl[base + (size_t)(s + 8) * 32] = lo;
            } else if (mode <= 3) {
                int h = col >> 5, d = (col & 31) + (mode == 3 ? 32 : 0);
                size_t base = ((size_t)(b * 16 + h) * 1024) * 64 + d;
                uint32_t hi, lo;
                split2(v01.x, v01.y, hi, lo);
                *(uint32_t*)&g_Vh[base + (size_t)s * 64] = hi;
                *(uint32_t*)&g_Vl[base + (size_t)s * 64] = lo;
                split2(v23.x, v23.y, hi, lo);
                *(uint32_t*)&g_Vh[base + (size_t)(s + 8) * 64] = hi;
                *(uint32_t*)&g_Vl[base + (size_t)(s + 8) * 64] = lo;
            } else {
                int half = mode - 4;
                size_t idx0 = (size_t)row * 1024 + half * 512 + col;
                size_t idx1 = idx0 + 8 * 1024;
                float2 r0 = *(const float2*)&inQ[idx0];
                float2 r1 = *(const float2*)&inQ[idx1];
                *(float2*)&g_tmp[idx0] = make_float2(v01.x + r0.x, v01.y + r0.y);
                *(float2*)&g_tmp[idx1] = make_float2(v23.x + r1.x, v23.y + r1.y);
            }
        }
    }
}

// ===========================================================================
// HMMA attention. CTA = (bh, 32-row q-slab), 256 threads (8 warps).
// Phase A: S = Q@K^T (split-3 HMMA) -> fp32 smem strip [32][<=1024].
// Phase B: row max, E=exp(s-m) back into smem (+l), write P=E/l to gmem.
// Phase C: O = (E@V)/l via split-3 HMMA, E converted per 64-chunk.
// ===========================================================================
#define SPITCH 1036
#define OFF_Q_H  132608
#define OFF_Q_L  135168
#define OFF_K_H  137728
#define OFF_K_L  142848
#define OFF_V_H  137728
#define OFF_V_L  146944
#define OFF_P_H  156160
#define OFF_P_L  160768
#define OFF_LINV 165376
#define ATTN_SMEM (165376 + 128)

__global__ void __launch_bounds__(256, 1)
attn_mma(float* __restrict__ Pout)
{
    extern __shared__ unsigned char sm[];
    float* Sb = (float*)sm;
    unsigned char* Qh = sm + OFF_Q_H;
    unsigned char* Ql = sm + OFF_Q_L;
    unsigned char* Kh = sm + OFF_K_H;
    unsigned char* Kl = sm + OFF_K_L;
    unsigned char* Vh = sm + OFF_V_H;
    unsigned char* Vl = sm + OFF_V_L;
    unsigned char* Ph = sm + OFF_P_H;
    unsigned char* Pl = sm + OFF_P_L;
    float* lArr = (float*)(sm + OFF_LINV);

    const int bh = blockIdx.x;
    const int qs = blockIdx.y;
    const int q0 = qs * 32;
    const int nkt = (q0 + 32 + 63) >> 6;
    const int ncol = nkt * 64;
    const int tid = threadIdx.x, wid = tid >> 5, lane = tid & 31;

    // ---- load Q slab (32 x 32 bf16, hi/lo) into smem staging ----
    {
        const __nv_bfloat16* srch = g_Q1h + ((size_t)bh * 1024 + q0) * 32;
        const __nv_bfloat16* srcl = g_Q1l + ((size_t)bh * 1024 + q0) * 32;
        int row = tid >> 3, seg = tid & 7;
        *(uint2*)(Qh + row * 80 + seg * 8) = *(const uint2*)(srch + row * 32 + seg * 4);
        *(uint2*)(Ql + row * 80 + seg * 8) = *(const uint2*)(srcl + row * 32 + seg * 4);
    }
    __syncthreads();

    // ---- Q fragments (held in regs all kernel) ----
    uint32_t qfh[2][2][4], qfl[2][2][4];   // [mt][ks][reg]
    {
        const uint32_t qh_b = smem_u32(Qh);
        const uint32_t ql_b = smem_u32(Ql);
        #pragma unroll
        for (int mt = 0; mt < 2; ++mt)
            #pragma unroll
            for (int ks = 0; ks < 2; ++ks) {
                uint32_t off = (uint32_t)((mt * 16 + (lane & 15)) * 80
                                          + ks * 32 + ((lane >> 4) & 1) * 16);
                ldsm_x4(qfh[mt][ks][0], qfh[mt][ks][1], qfh[mt][ks][2], qfh[mt][ks][3], qh_b + off);
                ldsm_x4(qfl[mt][ks][0], qfl[mt][ks][1], qfl[mt][ks][2], qfl[mt][ks][3], ql_b + off);
            }
    }

    // ================= Phase A: S = Q @ K^T =================
    const uint32_t kh_b = smem_u32(Kh);
    const uint32_t kl_b = smem_u32(Kl);
    for (int kt = 0; kt < nkt; ++kt) {
        if (kt) __syncthreads();
        // fill K tile (64 x 32 bf16 hi/lo)
        {
            const __nv_bfloat16* srch = g_K1h + ((size_t)bh * 1024 + kt * 64) * 32;
            const __nv_bfloat16* srcl = g_K1l + ((size_t)bh * 1024 + kt * 64) * 32;
            #pragma unroll
            for (int it = 0; it < 2; ++it) {
                int idx = tid + it * 256;
                int row = idx >> 3, seg = idx & 7;
                *(uint2*)(Kh + row * 80 + seg * 8) = *(const uint2*)(srch + row * 32 + seg * 4);
                *(uint2*)(Kl + row * 80 + seg * 8) = *(const uint2*)(srcl + row * 32 + seg * 4);
            }
        }
        __syncthreads();

        float c[2][4] = {};
        #pragma unroll
        for (int ks = 0; ks < 2; ++ks) {
            uint32_t boff = (uint32_t)((wid * 8 + (lane & 7)) * 80
                                       + ks * 32 + ((lane >> 3) & 1) * 16);
            uint32_t bh0, bh1, bl0, bl1;
            ldsm_x2(bh0, bh1, kh_b + boff);
            ldsm_x2(bl0, bl1, kl_b + boff);
            #pragma unroll
            for (int mt = 0; mt < 2; ++mt) {
                mma_bf16(c[mt], qfh[mt][ks][0], qfh[mt][ks][1], qfh[mt][ks][2], qfh[mt][ks][3], bh0, bh1);
                mma_bf16(c[mt], qfh[mt][ks][0], qfh[mt][ks][1], qfh[mt][ks][2], qfh[mt][ks][3], bl0, bl1);
                mma_bf16(c[mt], qfl[mt][ks][0], qfl[mt][ks][1], qfl[mt][ks][2], qfl[mt][ks][3], bh0, bh1);
            }
        }
        // store S fragments
        int scol = kt * 64 + wid * 8 + (lane & 3) * 2;
        int srow = lane >> 2;
        #pragma unroll
        for (int mt = 0; mt < 2; ++mt) {
            *(float2*)&Sb[(mt * 16 + srow) * SPITCH + scol]     = make_float2(c[mt][0], c[mt][1]);
            *(float2*)&Sb[(mt * 16 + srow + 8) * SPITCH + scol] = make_float2(c[mt][2], c[mt][3]);
        }
    }
    __syncthreads();

    // ================= Phase B: softmax =================
    #pragma unroll
    for (int j = 0; j < 4; ++j) {
        const int row = wid * 4 + j;
        const int limit = q0 + row;     // inclusive causal limit
        float* srow = &Sb[row * SPITCH];
        // max scan
        float m = -1e30f;
        for (int col = lane * 4; col < ncol; col += 128) {
            float4 s = *(const float4*)&srow[col];
            if (col + 0 <= limit) m = fmaxf(m, s.x);
            if (col + 1 <= limit) m = fmaxf(m, s.y);
            if (col + 2 <= limit) m = fmaxf(m, s.z);
            if (col + 3 <= limit) m = fmaxf(m, s.w);
        }
        #pragma unroll
        for (int off = 16; off > 0; off >>= 1)
            m = fmaxf(m, __shfl_xor_sync(0xffffffffu, m, off));
        // E = exp(s-m), store back, accumulate l
        float l = 0.f;
        for (int col = lane * 4; col < ncol; col += 128) {
            float4 s = *(const float4*)&srow[col];
            float4 e;
            e.x = (col + 0 <= limit) ? __expf(s.x - m) : 0.f;
            e.y = (col + 1 <= limit) ? __expf(s.y - m) : 0.f;
            e.z = (col + 2 <= limit) ? __expf(s.z - m) : 0.f;
            e.w = (col + 3 <= limit) ? __expf(s.w - m) : 0.f;
            *(float4*)&srow[col] = e;
            l += e.x + e.y + e.z + e.w;
        }
        #pragma unroll
        for (int off = 16; off > 0; off >>= 1)
            l += __shfl_xor_sync(0xffffffffu, l, off);
        float linv = 1.0f / l;
        if (lane == 0) lArr[row] = linv;
        // write P = E * linv (coalesced), zero tail
        float* prow = Pout + ((size_t)bh * 1024 + q0 + row) * 1024;
        for (int col = lane * 4; col < ncol; col += 128) {
            float4 e = *(const float4*)&srow[col];
            *(float4*)&prow[col] = make_float4(e.x * linv, e.y * linv, e.z * linv, e.w * linv);
        }
        float4 z4 = make_float4(0.f, 0.f, 0.f, 0.f);
        for (int col = ncol + lane * 4; col < 1024; col += 128)
            *(float4*)&prow[col] = z4;
    }

    // ================= Phase C: O = (E @ V) * linv =================
    const uint32_t vh_b = smem_u32(Vh);
    const uint32_t vl_b = smem_u32(Vl);
    const uint32_t ph_b = smem_u32(Ph);
    const uint32_t pl_b = smem_u32(Pl);
    float o[2][4] = {};

    for (int kt = 0; kt < nkt; ++kt) {
        __syncthreads();   // protect staging (also orders phase B for kt=0)
        // fill V tile (64 x 64 bf16 hi/lo)
        {
            const __nv_bfloat16* srch = g_Vh + ((size_t)bh * 1024 + kt * 64) * 64;
            const __nv_bfloat16* srcl = g_Vl + ((size_t)bh * 1024 + kt * 64) * 64;
            #pragma unroll
            for (int it = 0; it < 4; ++it) {
                int idx = tid + it * 256;
                int row = idx >> 4, seg = idx & 15;
                *(uint2*)(Vh + row * 144 + seg * 8) = *(const uint2*)(srch + row * 64 + seg * 4);
                *(uint2*)(Vl + row * 144 + seg * 8) = *(const uint2*)(srcl + row * 64 + seg * 4);
            }
        }
        // convert E chunk [32][64] fp32 -> bf16 hi/lo
        {
            int row = tid >> 3, c8 = (tid & 7) * 8;
            const float* src = &Sb[row * SPITCH + kt * 64 + c8];
            uint32_t hh[4], ll[4];
            #pragma unroll
            for (int u = 0; u < 4; ++u) {
                split2(src[u * 2], src[u * 2 + 1], hh[u], ll[u]);
            }
            *(uint4*)(Ph + row * 144 + c8 * 2) = make_uint4(hh[0], hh[1], hh[2], hh[3]);
            *(uint4*)(Pl + row * 144 + c8 * 2) = make_uint4(ll[0], ll[1], ll[2], ll[3]);
        }
        __syncthreads();

        #pragma unroll
        for (int ks = 0; ks < 4; ++ks) {
            uint32_t aoff = (uint32_t)(((lane & 15)) * 144 + ks * 32 + ((lane >> 4) & 1) * 16);
            uint32_t boff = (uint32_t)((ks * 16 + (lane & 15)) * 144 + (wid * 8) * 2);
            uint32_t vb0, vb1, wb0, wb1;
            ldsm_x2t(vb0, vb1, vh_b + boff);
            ldsm_x2t(wb0, wb1, vl_b + boff);
            #pragma unroll
            for (int mt = 0; mt < 2; ++mt) {
                uint32_t pa[4], qa[4];
                ldsm_x4(pa[0], pa[1], pa[2], pa[3], ph_b + aoff + (uint32_t)(mt * 16 * 144));
                ldsm_x4(qa[0], qa[1], qa[2], qa[3], pl_b + aoff + (uint32_t)(mt * 16 * 144));
                mma_bf16(o[mt], pa[0], pa[1], pa[2], pa[3], vb0, vb1);
                mma_bf16(o[mt], pa[0], pa[1], pa[2], pa[3], wb0, wb1);
                mma_bf16(o[mt], qa[0], qa[1], qa[2], qa[3], vb0, vb1);
            }
        }
    }

    // ---- epilogue: scale by linv, write g_qkv ----
    const int b = bh >> 4, h = bh & 15;
    const int dv = h * 64 + wid * 8 + (lane & 3) * 2;
    #pragma unroll
    for (int mt = 0; mt < 2; ++mt) {
        int r0 = mt * 16 + (lane >> 2);
        int r1 = r0 + 8;
        float li0 = lArr[r0], li1 = lArr[r1];
        size_t i0 = ((size_t)(b * 1024 + q0 + r0)) * 1024 + dv;
        size_t i1 = ((size_t)(b * 1024 + q0 + r1)) * 1024 + dv;
        *(float2*)&g_qkv[i0] = make_float2(o[mt][0] * li0, o[mt][1] * li0);
        *(float2*)&g_qkv[i1] = make_float2(o[mt][2] * li1, o[mt][3] * li1);
    }
}

// ---------------------------------------------------------------------------
// LayerNorm (unchanged)
// ---------------------------------------------------------------------------
__global__ void ln_kernel(const float* __restrict__ gamma,
                          const float* __restrict__ beta,
                          float* __restrict__ out)
{
    const int row = blockIdx.x >> 1;
    const int half = blockIdx.x & 1;
    const float* x = g_tmp + (size_t)row * 1024 + half * 512;
    const int tid = threadIdx.x;

    float v0 = x[tid], v1 = x[tid + 256];
    float s = v0 + v1;
    float sq = v0 * v0 + v1 * v1;
    #pragma unroll
    for (int off = 16; off > 0; off >>= 1) {
        s  += __shfl_xor_sync(0xffffffffu, s,  off);
        sq += __shfl_xor_sync(0xffffffffu, sq, off);
    }
    __shared__ float ss[8], sqq[8];
    if ((tid & 31) == 0) { ss[tid >> 5] = s; sqq[tid >> 5] = sq; }
    __syncthreads();
    float tot = 0.f, totq = 0.f;
    #pragma unroll
    for (int w = 0; w < 8; w++) { tot += ss[w]; totq += sqq[w]; }

    float mu = tot * (1.0f / 512.0f);
    float var = totq * (1.0f / 512.0f) - mu * mu;
    float rstd = rsqrtf(var + 1e-5f);

    size_t obase = (size_t)row * 1024 + half * 512;
    out[obase + tid]       = (v0 - mu) * rstd * gamma[tid]       + beta[tid];
    out[obase + tid + 256] = (v1 - mu) * rstd * gamma[tid + 256] + beta[tid + 256];
}

// ---------------------------------------------------------------------------
extern "C" void kernel_launch(void* const* d_in, const int* in_sizes, int n_in,
                              void* d_out, int out_size)
{
    const float* inQ  = (const float*)d_in[0];
    const float* inK  = (const float*)d_in[1];
    const float* inV  = (const float*)d_in[2];
    const float* WQ1  = (const float*)d_in[4];
    const float* WK1  = (const float*)d_in[5];
    const float* WV1  = (const float*)d_in[6];
    const float* WV2  = (const float*)d_in[9];
    const float* Wfc1 = (const float*)d_in[10];
    const float* Wfc2 = (const float*)d_in[11];
    const float* ln_g = (const float*)d_in[12];
    const float* ln_b = (const float*)d_in[13];

    float* out  = (float*)d_out;
    float* Pout = out + (size_t)B_ * S_ * D_;

    cudaFuncSetAttribute(attn_mma, cudaFuncAttributeMaxDynamicSharedMemorySize,
                         ATTN_SMEM);

    // Projections: Q1, K1, V1, V2  (HMMA bf16 split-2, bf16 split outputs)
    mma_gemm<<<dim3(32, 4, 4), 256>>>(inQ, inK, inV, WQ1, WK1, WV1, WV2, 0);
    // Attention: S once, softmax + P output, O = E@V / l
    attn_mma<<<dim3(64, 32), 256, ATTN_SMEM>>>(Pout);
    // FC + residual (HMMA)
    mma_gemm<<<dim3(32, 4, 2), 256>>>(inQ, inK, inV, Wfc1, Wfc2, Wfc1, Wfc2, 4);
    // LayerNorm -> final output
    ln_kernel<<<dim3(B_ * S_ * 2), 256>>>(ln_g, ln_b, out);
}

// round 5
// speedup vs baseline: 1.7629x; 1.2076x over previous
#include <cuda_runtime.h>
#include <cuda_bf16.h>
#include <math.h>
#include <stdint.h>

// Problem constants
#define B_  4
#define S_  1024
#define D_  1024
#define H_  16
#define DKH_ 32
#define DV_  64

// ---------------------------------------------------------------------------
// Scratch (device globals; no allocations allowed)
// ---------------------------------------------------------------------------
// pre-split GEMM A operands (bf16 hi/lo)
__device__ __nv_bfloat16 pQh[4096*512],  pQl[4096*512];    // inQ[:, :512]
__device__ __nv_bfloat16 pKh[4096*512],  pKl[4096*512];    // inK[:, :512]
__device__ __nv_bfloat16 pVh_[4096*1024], pVl_[4096*1024]; // inV (full)
__device__ __nv_bfloat16 pWh[6*512*512], pWl[6*512*512];   // 6 weight mats [k][n]
// projection outputs (bf16 hi/lo), attention inputs
__device__ __nv_bfloat16 g_Q1h[64*1024*32], g_Q1l[64*1024*32]; // pre-scaled
__device__ __nv_bfloat16 g_K1h[64*1024*32], g_K1l[64*1024*32];
__device__ __nv_bfloat16 g_Vh [64*1024*64], g_Vl [64*1024*64];
// attention output (bf16 hi/lo) = FC A operand
__device__ __nv_bfloat16 qkvh[4096*1024], qkvl[4096*1024];
// FC + residual (fp32, pre-LN)
__device__ float g_tmp[B_*S_*D_];

// ===========================================================================
// helpers
// ===========================================================================
__device__ __forceinline__ uint32_t smem_u32(const void* p) {
    uint32_t a;
    asm("{ .reg .u64 t; cvta.to.shared.u64 t, %1; cvt.u32.u64 %0, t; }"
        : "=r"(a) : "l"(p));
    return a;
}
__device__ __forceinline__ void ldsm_x4(uint32_t& r0, uint32_t& r1,
                                        uint32_t& r2, uint32_t& r3, uint32_t addr) {
    asm volatile("ldmatrix.sync.aligned.m8n8.x4.shared.b16 {%0,%1,%2,%3}, [%4];"
                 : "=r"(r0), "=r"(r1), "=r"(r2), "=r"(r3) : "r"(addr));
}
__device__ __forceinline__ void ldsm_x2(uint32_t& r0, uint32_t& r1, uint32_t addr) {
    asm volatile("ldmatrix.sync.aligned.m8n8.x2.shared.b16 {%0,%1}, [%2];"
                 : "=r"(r0), "=r"(r1) : "r"(addr));
}
__device__ __forceinline__ void ldsm_x2t(uint32_t& r0, uint32_t& r1, uint32_t addr) {
    asm volatile("ldmatrix.sync.aligned.m8n8.x2.trans.shared.b16 {%0,%1}, [%2];"
                 : "=r"(r0), "=r"(r1) : "r"(addr));
}
__device__ __forceinline__ void mma_bf16(float* c, uint32_t a0, uint32_t a1,
                                         uint32_t a2, uint32_t a3,
                                         uint32_t b0, uint32_t b1) {
    asm volatile("mma.sync.aligned.m16n8k16.row.col.f32.bf16.bf16.f32 "
                 "{%0,%1,%2,%3}, {%4,%5,%6,%7}, {%8,%9}, {%0,%1,%2,%3};"
                 : "+f"(c[0]), "+f"(c[1]), "+f"(c[2]), "+f"(c[3])
                 : "r"(a0), "r"(a1), "r"(a2), "r"(a3), "r"(b0), "r"(b1));
}
__device__ __forceinline__ uint32_t pack_bf16(__nv_bfloat16 a, __nv_bfloat16 b) {
    __nv_bfloat162 t; t.x = a; t.y = b;
    return *reinterpret_cast<uint32_t*>(&t);
}
__device__ __forceinline__ void split2(float x, float y, uint32_t& hi, uint32_t& lo) {
    __nv_bfloat16 hx = __float2bfloat16_rn(x);
    __nv_bfloat16 hy = __float2bfloat16_rn(y);
    __nv_bfloat16 lx = __float2bfloat16_rn(x - __bfloat162float(hx));
    __nv_bfloat16 ly = __float2bfloat16_rn(y - __bfloat162float(hy));
    hi = pack_bf16(hx, hy);
    lo = pack_bf16(lx, ly);
}
__device__ __forceinline__ void cp16(uint32_t dst, const void* src) {
    asm volatile("cp.async.cg.shared.global [%0], [%1], 16;"
                 :: "r"(dst), "l"(src));
}
#define CP_COMMIT()  asm volatile("cp.async.commit_group;" ::: "memory")
#define CP_WAIT(N)   asm volatile("cp.async.wait_group %0;" :: "n"(N) : "memory")

// ===========================================================================
// presplit: fp32 -> bf16 hi/lo for all GEMM operands.
// blockIdx.y: 0=Qh0, 1=Kh0, 2=V, 3..8=W0..W5
// ===========================================================================
__global__ void __launch_bounds__(256)
presplit(const float* __restrict__ inQ, const float* __restrict__ inK,
         const float* __restrict__ inV,
         const float* __restrict__ W0, const float* __restrict__ W1,
         const float* __restrict__ W2, const float* __restrict__ W3,
         const float* __restrict__ W4, const float* __restrict__ W5)
{
    const int seg = blockIdx.y;
    const int gid = blockIdx.x * 256 + threadIdx.x;
    const int stride4 = gridDim.x * 256 * 4;

    if (seg < 2) {
        const float* s = seg ? inK : inQ;
        __nv_bfloat16* dh = seg ? pKh : pQh;
        __nv_bfloat16* dl = seg ? pKl : pQl;
        for (int i = gid * 4; i < 4096 * 512; i += stride4) {
            int row = i >> 9, col = i & 511;
            float4 v = *(const float4*)&s[(size_t)row * 1024 + col];
            uint32_t h0, l0, h1, l1;
            split2(v.x, v.y, h0, l0); split2(v.z, v.w, h1, l1);
            *(uint2*)&dh[i] = make_uint2(h0, h1);
            *(uint2*)&dl[i] = make_uint2(l0, l1);
        }
    } else if (seg == 2) {
        for (int i = gid * 4; i < 4096 * 1024; i += stride4) {
            float4 v = *(const float4*)&inV[i];
            uint32_t h0, l0, h1, l1;
            split2(v.x, v.y, h0, l0); split2(v.z, v.w, h1, l1);
            *(uint2*)&pVh_[i] = make_uint2(h0, h1);
            *(uint2*)&pVl_[i] = make_uint2(l0, l1);
        }
    } else {
        const int w = seg - 3;
        const float* s = (w == 0) ? W0 : (w == 1) ? W1 : (w == 2) ? W2
                       : (w == 3) ? W3 : (w == 4) ? W4 : W5;
        __nv_bfloat16* dh = pWh + (size_t)w * 262144;
        __nv_bfloat16* dl = pWl + (size_t)w * 262144;
        for (int i = gid * 4; i < 262144; i += stride4) {
            float4 v = *(const float4*)&s[i];
            uint32_t h0, l0, h1, l1;
            split2(v.x, v.y, h0, l0); split2(v.z, v.w, h1, l1);
            *(uint2*)&dh[i] = make_uint2(h0, h1);
            *(uint2*)&dl[i] = make_uint2(l0, l1);
        }
    }
}

// ===========================================================================
// HMMA GEMM, cp.async double-buffered. CTA tile 128x128, 8 warps, K chunk 32.
// mode: 0=Q1(->split,scaled), 1=K1(->split), 2=V1, 3=V2,
//       4=FC half0 (+res fp32), 5=FC half1 (+res fp32)
// ===========================================================================
#define APITCH 80
#define BPITCH 272
#define G_AH(buf) ((buf) * 10240u)
#define G_AL(buf) (20480u + (buf) * 10240u)
#define G_BH(buf) (40960u + (buf) * 8704u)
#define G_BL(buf) (58368u + (buf) * 8704u)
#define GEMM_SMEM 75776

__global__ void __launch_bounds__(256, 1)
mma_gemm(const float* __restrict__ inQ, int mode_base)
{
    extern __shared__ unsigned char sm[];
    const uint32_t smb = smem_u32(sm);

    const int mode = mode_base + blockIdx.z;
    const __nv_bfloat16 *pAh, *pAl;
    int apitch, aoff;
    switch (mode) {
        case 0: pAh = pQh;  pAl = pQl;  apitch = 512;  aoff = 0;   break;
        case 1: pAh = pKh;  pAl = pKl;  apitch = 512;  aoff = 0;   break;
        case 2: pAh = pVh_; pAl = pVl_; apitch = 1024; aoff = 0;   break;
        case 3: pAh = pVh_; pAl = pVl_; apitch = 1024; aoff = 512; break;
        case 4: pAh = qkvh; pAl = qkvl; apitch = 1024; aoff = 0;   break;
        default:pAh = qkvh; pAl = qkvl; apitch = 1024; aoff = 512; break;
    }
    const __nv_bfloat16* wh = pWh + (size_t)mode * 262144;
    const __nv_bfloat16* wl = pWl + (size_t)mode * 262144;

    const int m0 = blockIdx.x * 128;
    const int n0 = blockIdx.y * 128;
    const int tid  = threadIdx.x;
    const int wid  = tid >> 5;
    const int lane = tid & 31;
    const int wy = wid >> 2;
    const int wx = wid & 3;

    // fill helper (lambda-free): issues 8 cp.async per thread
    const int ar = tid >> 2, aseg = tid & 3;          // A: 64 rows x 4 segs x (it 0..1)
    const int br = tid >> 4, bseg = tid & 15;         // B: 16 rows x 16 segs x (it 0..1)

    #define GFILL(buf, k0)                                                        \
    {                                                                             \
        _Pragma("unroll")                                                         \
        for (int it = 0; it < 2; ++it) {                                          \
            int row = ar + it * 64;                                               \
            const __nv_bfloat16* sh = pAh + (size_t)(m0 + row) * apitch + aoff + (k0) + aseg * 8; \
            const __nv_bfloat16* sl = pAl + (size_t)(m0 + row) * apitch + aoff + (k0) + aseg * 8; \
            uint32_t d = (uint32_t)(row * APITCH + aseg * 16);                    \
            cp16(smb + G_AH(buf) + d, sh);                                        \
            cp16(smb + G_AL(buf) + d, sl);                                        \
        }                                                                         \
        _Pragma("unroll")                                                         \
        for (int it = 0; it < 2; ++it) {                                          \
            int row = br + it * 16;                                               \
            const __nv_bfloat16* sh = wh + (size_t)((k0) + row) * 512 + n0 + bseg * 8; \
            const __nv_bfloat16* sl = wl + (size_t)((k0) + row) * 512 + n0 + bseg * 8; \
            uint32_t d = (uint32_t)(row * BPITCH + bseg * 16);                    \
            cp16(smb + G_BH(buf) + d, sh);                                        \
            cp16(smb + G_BL(buf) + d, sl);                                        \
        }                                                                         \
        CP_COMMIT();                                                              \
    }

    float c[4][4][4] = {};

    const int a_row_in_tile = lane & 15;
    const int a_kseg        = (lane >> 4) & 1;
    const int b_krow        = (lane & 7) + ((lane >> 3) & 1) * 8;

    GFILL(0, 0);

    for (int chunk = 0; chunk < 16; ++chunk) {
        if (chunk + 1 < 16) { GFILL((chunk + 1) & 1, (chunk + 1) * 32); CP_WAIT(1); }
        else                { CP_WAIT(0); }
        __syncthreads();

        const uint32_t ahb = smb + G_AH(chunk & 1);
        const uint32_t alb = smb + G_AL(chunk & 1);
        const uint32_t bhb = smb + G_BH(chunk & 1);
        const uint32_t blb = smb + G_BL(chunk & 1);

        #pragma unroll
        for (int ks = 0; ks < 2; ++ks) {
            uint32_t ahf[4][4], alf[4][4];
            #pragma unroll
            for (int mt = 0; mt < 4; ++mt) {
                int row = wy * 64 + mt * 16 + a_row_in_tile;
                uint32_t aoffb = (uint32_t)(row * APITCH + ks * 32 + a_kseg * 16);
                ldsm_x4(ahf[mt][0], ahf[mt][1], ahf[mt][2], ahf[mt][3], ahb + aoffb);
                ldsm_x4(alf[mt][0], alf[mt][1], alf[mt][2], alf[mt][3], alb + aoffb);
            }
            uint32_t bhf[4][2], blf[4][2];
            #pragma unroll
            for (int nt = 0; nt < 4; ++nt) {
                uint32_t boffb = (uint32_t)((ks * 16 + b_krow) * BPITCH
                                            + (wx * 32 + nt * 8) * 2);
                ldsm_x2t(bhf[nt][0], bhf[nt][1], bhb + boffb);
                ldsm_x2t(blf[nt][0], blf[nt][1], blb + boffb);
            }
            #pragma unroll
            for (int mt = 0; mt < 4; ++mt) {
                #pragma unroll
                for (int nt = 0; nt < 4; ++nt) {
                    mma_bf16(c[mt][nt], ahf[mt][0], ahf[mt][1], ahf[mt][2], ahf[mt][3],
                             bhf[nt][0], bhf[nt][1]);
                    mma_bf16(c[mt][nt], ahf[mt][0], ahf[mt][1], ahf[mt][2], ahf[mt][3],
                             blf[nt][0], blf[nt][1]);
                    mma_bf16(c[mt][nt], alf[mt][0], alf[mt][1], alf[mt][2], alf[mt][3],
                             bhf[nt][0], bhf[nt][1]);
                }
            }
        }
        __syncthreads();
    }

    // ---- epilogue ----
    const int gid = lane >> 2;
    const int tig = lane & 3;

    #pragma unroll
    for (int mt = 0; mt < 4; ++mt) {
        int row = m0 + wy * 64 + mt * 16 + gid;
        int b = row >> 10, s = row & 1023;
        #pragma unroll
        for (int nt = 0; nt < 4; ++nt) {
            int col = n0 + wx * 32 + nt * 8 + tig * 2;
            float2 v01 = make_float2(c[mt][nt][0], c[mt][nt][1]);
            float2 v23 = make_float2(c[mt][nt][2], c[mt][nt][3]);
            if (mode <= 1) {
                int h = col >> 5, d = col & 31;
                __nv_bfloat16* dh = (mode == 0) ? g_Q1h : g_K1h;
                __nv_bfloat16* dl = (mode == 0) ? g_Q1l : g_K1l;
                float sc = (mode == 0) ? 0.17677669529663688f : 1.0f;
                size_t base = ((size_t)(b * 16 + h) * 1024) * 32 + d;
                uint32_t hi, lo;
                split2(v01.x * sc, v01.y * sc, hi, lo);
                *(uint32_t*)&dh[base + (size_t)s * 32] = hi;
                *(uint32_t*)&dl[base + (size_t)s * 32] = lo;
                split2(v23.x * sc, v23.y * sc, hi, lo);
                *(uint32_t*)&dh[base + (size_t)(s + 8) * 32] = hi;
                *(uint32_t*)&dl[base + (size_t)(s + 8) * 32] = lo;
            } else if (mode <= 3) {
                int h = col >> 5, d = (col & 31) + (mode == 3 ? 32 : 0);
                size_t base = ((size_t)(b * 16 + h) * 1024) * 64 + d;
                uint32_t hi, lo;
                split2(v01.x, v01.y, hi, lo);
                *(uint32_t*)&g_Vh[base + (size_t)s * 64] = hi;
                *(uint32_t*)&g_Vl[base + (size_t)s * 64] = lo;
                split2(v23.x, v23.y, hi, lo);
                *(uint32_t*)&g_Vh[base + (size_t)(s + 8) * 64] = hi;
                *(uint32_t*)&g_Vl[base + (size_t)(s + 8) * 64] = lo;
            } else {
                int half = mode - 4;
                size_t idx0 = (size_t)row * 1024 + half * 512 + col;
                size_t idx1 = idx0 + 8 * 1024;
                float2 r0 = *(const float2*)&inQ[idx0];
                float2 r1 = *(const float2*)&inQ[idx1];
                *(float2*)&g_tmp[idx0] = make_float2(v01.x + r0.x, v01.y + r0.y);
                *(float2*)&g_tmp[idx1] = make_float2(v23.x + r1.x, v23.y + r1.y);
            }
        }
    }
    #undef GFILL
}

// ===========================================================================
// HMMA attention, cp.async double-buffered K (phase A) and V (phase C).
// CTA = (bh, 32-row q-slab, LPT order), 256 threads.
// ===========================================================================
#define SPITCH 1036
#define OFF_Q_H  132608
#define OFF_Q_L  135168
#define OFF_K_H(buf)  (137728u + (buf) * 5120u)
#define OFF_K_L(buf)  (147968u + (buf) * 5120u)
#define OFF_V_H(buf)  (137728u + (buf) * 9216u)
#define OFF_V_L(buf)  (156160u + (buf) * 9216u)
#define OFF_P_H  174592
#define OFF_P_L  179200
#define OFF_LINV 183808
#define ATTN_SMEM (183808 + 128)

__global__ void __launch_bounds__(256, 1)
attn_mma(float* __restrict__ Pout)
{
    extern __shared__ unsigned char sm[];
    float* Sb = (float*)sm;
    float* lArr = (float*)(sm + OFF_LINV);
    const uint32_t smb = smem_u32(sm);

    const int bh = blockIdx.x;
    const int qs = 31 - blockIdx.y;       // LPT: heavy slabs first
    const int q0 = qs * 32;
    const int nkt = (q0 + 32 + 63) >> 6;
    const int ncol = nkt * 64;
    const int tid = threadIdx.x, wid = tid >> 5, lane = tid & 31;

    // K fill: 64 rows x 4 segs (hi & lo), 2 cp per thread
    const int kr = tid >> 2, kseg = tid & 3;
    #define KFILL(buf, kt)                                                        \
    {                                                                             \
        const __nv_bfloat16* sh = g_K1h + ((size_t)bh * 1024 + (kt) * 64 + kr) * 32 + kseg * 8; \
        const __nv_bfloat16* sl = g_K1l + ((size_t)bh * 1024 + (kt) * 64 + kr) * 32 + kseg * 8; \
        uint32_t d = (uint32_t)(kr * 80 + kseg * 16);                             \
        cp16(smb + OFF_K_H(buf) + d, sh);                                         \
        cp16(smb + OFF_K_L(buf) + d, sl);                                         \
        CP_COMMIT();                                                              \
    }
    // V fill: 64 rows x 8 segs (hi & lo), 4 cp per thread
    const int vr = tid >> 3, vseg = tid & 7;
    #define VFILL(buf, kt)                                                        \
    {                                                                             \
        _Pragma("unroll")                                                         \
        for (int it = 0; it < 2; ++it) {                                          \
            int row = vr + it * 32;                                               \
            const __nv_bfloat16* sh = g_Vh + ((size_t)bh * 1024 + (kt) * 64 + row) * 64 + vseg * 8; \
            const __nv_bfloat16* sl = g_Vl + ((size_t)bh * 1024 + (kt) * 64 + row) * 64 + vseg * 8; \
            uint32_t d = (uint32_t)(row * 144 + vseg * 16);                       \
            cp16(smb + OFF_V_H(buf) + d, sh);                                     \
            cp16(smb + OFF_V_L(buf) + d, sl);                                     \
        }                                                                         \
        CP_COMMIT();                                                              \
    }

    // prefetch K tile 0
    KFILL(0, 0);

    // ---- load Q slab (32 x 32 bf16, hi/lo) ----
    {
        const __nv_bfloat16* srch = g_Q1h + ((size_t)bh * 1024 + q0) * 32;
        const __nv_bfloat16* srcl = g_Q1l + ((size_t)bh * 1024 + q0) * 32;
        int row = tid >> 3, seg = tid & 7;
        *(uint2*)(sm + OFF_Q_H + row * 80 + seg * 8) = *(const uint2*)(srch + row * 32 + seg * 4);
        *(uint2*)(sm + OFF_Q_L + row * 80 + seg * 8) = *(const uint2*)(srcl + row * 32 + seg * 4);
    }
    __syncthreads();

    // ---- Q fragments (regs) ----
    uint32_t qfh[2][2][4], qfl[2][2][4];
    {
        #pragma unroll
        for (int mt = 0; mt < 2; ++mt)
            #pragma unroll
            for (int ks = 0; ks < 2; ++ks) {
                uint32_t off = (uint32_t)((mt * 16 + (lane & 15)) * 80
                                          + ks * 32 + ((lane >> 4) & 1) * 16);
                ldsm_x4(qfh[mt][ks][0], qfh[mt][ks][1], qfh[mt][ks][2], qfh[mt][ks][3],
                        smb + OFF_Q_H + off);
                ldsm_x4(qfl[mt][ks][0], qfl[mt][ks][1], qfl[mt][ks][2], qfl[mt][ks][3],
                        smb + OFF_Q_L + off);
            }
    }

    // ================= Phase A: S = Q @ K^T =================
    for (int kt = 0; kt < nkt; ++kt) {
        if (kt + 1 < nkt) { KFILL((kt + 1) & 1, kt + 1); CP_WAIT(1); }
        else              { CP_WAIT(0); }
        __syncthreads();

        const uint32_t khb = smb + OFF_K_H(kt & 1);
        const uint32_t klb = smb + OFF_K_L(kt & 1);

        float c[2][4] = {};
        #pragma unroll
        for (int ks = 0; ks < 2; ++ks) {
            uint32_t boff = (uint32_t)((wid * 8 + (lane & 7)) * 80
                                       + ks * 32 + ((lane >> 3) & 1) * 16);
            uint32_t bh0, bh1, bl0, bl1;
            ldsm_x2(bh0, bh1, khb + boff);
            ldsm_x2(bl0, bl1, klb + boff);
            #pragma unroll
            for (int mt = 0; mt < 2; ++mt) {
                mma_bf16(c[mt], qfh[mt][ks][0], qfh[mt][ks][1], qfh[mt][ks][2], qfh[mt][ks][3], bh0, bh1);
                mma_bf16(c[mt], qfh[mt][ks][0], qfh[mt][ks][1], qfh[mt][ks][2], qfh[mt][ks][3], bl0, bl1);
                mma_bf16(c[mt], qfl[mt][ks][0], qfl[mt][ks][1], qfl[mt][ks][2], qfl[mt][ks][3], bh0, bh1);
            }
        }
        int scol = kt * 64 + wid * 8 + (lane & 3) * 2;
        int srow = lane >> 2;
        #pragma unroll
        for (int mt = 0; mt < 2; ++mt) {
            *(float2*)&Sb[(mt * 16 + srow) * SPITCH + scol]     = make_float2(c[mt][0], c[mt][1]);
            *(float2*)&Sb[(mt * 16 + srow + 8) * SPITCH + scol] = make_float2(c[mt][2], c[mt][3]);
        }
        __syncthreads();
    }

    // prefetch V tile 0 (overlaps phase B)
    VFILL(0, 0);

    // ================= Phase B: softmax =================
    #pragma unroll
    for (int j = 0; j < 4; ++j) {
        const int row = wid * 4 + j;
        const int limit = q0 + row;
        float* srow = &Sb[row * SPITCH];
        float m = -1e30f;
        for (int col = lane * 4; col < ncol; col += 128) {
            float4 s = *(const float4*)&srow[col];
            if (col + 0 <= limit) m = fmaxf(m, s.x);
            if (col + 1 <= limit) m = fmaxf(m, s.y);
            if (col + 2 <= limit) m = fmaxf(m, s.z);
            if (col + 3 <= limit) m = fmaxf(m, s.w);
        }
        #pragma unroll
        for (int off = 16; off > 0; off >>= 1)
            m = fmaxf(m, __shfl_xor_sync(0xffffffffu, m, off));
        float l = 0.f;
        for (int col = lane * 4; col < ncol; col += 128) {
            float4 s = *(const float4*)&srow[col];
            float4 e;
            e.x = (col + 0 <= limit) ? __expf(s.x - m) : 0.f;
            e.y = (col + 1 <= limit) ? __expf(s.y - m) : 0.f;
            e.z = (col + 2 <= limit) ? __expf(s.z - m) : 0.f;
            e.w = (col + 3 <= limit) ? __expf(s.w - m) : 0.f;
            *(float4*)&srow[col] = e;
            l += e.x + e.y + e.z + e.w;
        }
        #pragma unroll
        for (int off = 16; off > 0; off >>= 1)
            l += __shfl_xor_sync(0xffffffffu, l, off);
        float linv = 1.0f / l;
        if (lane == 0) lArr[row] = linv;
        float* prow = Pout + ((size_t)bh * 1024 + q0 + row) * 1024;
        for (int col = lane * 4; col < ncol; col += 128) {
            float4 e = *(const float4*)&srow[col];
            *(float4*)&prow[col] = make_float4(e.x * linv, e.y * linv, e.z * linv, e.w * linv);
        }
        float4 z4 = make_float4(0.f, 0.f, 0.f, 0.f);
        for (int col = ncol + lane * 4; col < 1024; col += 128)
            *(float4*)&prow[col] = z4;
    }

    // ================= Phase C: O = (E @ V) * linv =================
    float o[2][4] = {};

    for (int kt = 0; kt < nkt; ++kt) {
        if (kt + 1 < nkt) VFILL((kt + 1) & 1, kt + 1);
        // convert E chunk [32][64] fp32 -> bf16 hi/lo (own rows; no sync needed)
        {
            int row = tid >> 3, c8 = (tid & 7) * 8;
            const float* src = &Sb[row * SPITCH + kt * 64 + c8];
            uint32_t hh[4], ll[4];
            #pragma unroll
            for (int u = 0; u < 4; ++u)
                split2(src[u * 2], src[u * 2 + 1], hh[u], ll[u]);
            *(uint4*)(sm + OFF_P_H + row * 144 + c8 * 2) = make_uint4(hh[0], hh[1], hh[2], hh[3]);
            *(uint4*)(sm + OFF_P_L + row * 144 + c8 * 2) = make_uint4(ll[0], ll[1], ll[2], ll[3]);
        }
        if (kt + 1 < nkt) { CP_WAIT(1); } else { CP_WAIT(0); }
        __syncthreads();

        const uint32_t vhb = smb + OFF_V_H(kt & 1);
        const uint32_t vlb = smb + OFF_V_L(kt & 1);

        #pragma unroll
        for (int ks = 0; ks < 4; ++ks) {
            uint32_t aoff = (uint32_t)(((lane & 15)) * 144 + ks * 32 + ((lane >> 4) & 1) * 16);
            uint32_t boff = (uint32_t)((ks * 16 + (lane & 15)) * 144 + (wid * 8) * 2);
            uint32_t vb0, vb1, wb0, wb1;
            ldsm_x2t(vb0, vb1, vhb + boff);
            ldsm_x2t(wb0, wb1, vlb + boff);
            #pragma unroll
            for (int mt = 0; mt < 2; ++mt) {
                uint32_t pa[4], qa[4];
                ldsm_x4(pa[0], pa[1], pa[2], pa[3], smb + OFF_P_H + aoff + (uint32_t)(mt * 16 * 144));
                ldsm_x4(qa[0], qa[1], qa[2], qa[3], smb + OFF_P_L + aoff + (uint32_t)(mt * 16 * 144));
                mma_bf16(o[mt], pa[0], pa[1], pa[2], pa[3], vb0, vb1);
                mma_bf16(o[mt], pa[0], pa[1], pa[2], pa[3], wb0, wb1);
                mma_bf16(o[mt], qa[0], qa[1], qa[2], qa[3], vb0, vb1);
            }
        }
        __syncthreads();
    }

    // ---- epilogue: scale by linv, write qkvh/qkvl (bf16 split) ----
    const int b = bh >> 4, h = bh & 15;
    const int dv = h * 64 + wid * 8 + (lane & 3) * 2;
    #pragma unroll
    for (int mt = 0; mt < 2; ++mt) {
        int r0 = mt * 16 + (lane >> 2);
        int r1 = r0 + 8;
        float li0 = lArr[r0], li1 = lArr[r1];
        size_t i0 = ((size_t)(b * 1024 + q0 + r0)) * 1024 + dv;
        size_t i1 = ((size_t)(b * 1024 + q0 + r1)) * 1024 + dv;
        uint32_t hi, lo;
        split2(o[mt][0] * li0, o[mt][1] * li0, hi, lo);
        *(uint32_t*)&qkvh[i0] = hi; *(uint32_t*)&qkvl[i0] = lo;
        split2(o[mt][2] * li1, o[mt][3] * li1, hi, lo);
        *(uint32_t*)&qkvh[i1] = hi; *(uint32_t*)&qkvl[i1] = lo;
    }
    #undef KFILL
    #undef VFILL
}

// ---------------------------------------------------------------------------
// LayerNorm (unchanged)
// ---------------------------------------------------------------------------
__global__ void ln_kernel(const float* __restrict__ gamma,
                          const float* __restrict__ beta,
                          float* __restrict__ out)
{
    const int row = blockIdx.x >> 1;
    const int half = blockIdx.x & 1;
    const float* x = g_tmp + (size_t)row * 1024 + half * 512;
    const int tid = threadIdx.x;

    float v0 = x[tid], v1 = x[tid + 256];
    float s = v0 + v1;
    float sq = v0 * v0 + v1 * v1;
    #pragma unroll
    for (int off = 16; off > 0; off >>= 1) {
        s  += __shfl_xor_sync(0xffffffffu, s,  off);
        sq += __shfl_xor_sync(0xffffffffu, sq, off);
    }
    __shared__ float ss[8], sqq[8];
    if ((tid & 31) == 0) { ss[tid >> 5] = s; sqq[tid >> 5] = sq; }
    __syncthreads();
    float tot = 0.f, totq = 0.f;
    #pragma unroll
    for (int w = 0; w < 8; w++) { tot += ss[w]; totq += sqq[w]; }

    float mu = tot * (1.0f / 512.0f);
    float var = totq * (1.0f / 512.0f) - mu * mu;
    float rstd = rsqrtf(var + 1e-5f);

    size_t obase = (size_t)row * 1024 + half * 512;
    out[obase + tid]       = (v0 - mu) * rstd * gamma[tid]       + beta[tid];
    out[obase + tid + 256] = (v1 - mu) * rstd * gamma[tid + 256] + beta[tid + 256];
}

// ---------------------------------------------------------------------------
extern "C" void kernel_launch(void* const* d_in, const int* in_sizes, int n_in,
                              void* d_out, int out_size)
{
    const float* inQ  = (const float*)d_in[0];
    const float* inK  = (const float*)d_in[1];
    const float* inV  = (const float*)d_in[2];
    const float* WQ1  = (const float*)d_in[4];
    const float* WK1  = (const float*)d_in[5];
    const float* WV1  = (const float*)d_in[6];
    const float* WV2  = (const float*)d_in[9];
    const float* Wfc1 = (const float*)d_in[10];
    const float* Wfc2 = (const float*)d_in[11];
    const float* ln_g = (const float*)d_in[12];
    const float* ln_b = (const float*)d_in[13];

    float* out  = (float*)d_out;
    float* Pout = out + (size_t)B_ * S_ * D_;

    cudaFuncSetAttribute(attn_mma, cudaFuncAttributeMaxDynamicSharedMemorySize,
                         ATTN_SMEM);
    cudaFuncSetAttribute(mma_gemm, cudaFuncAttributeMaxDynamicSharedMemorySize,
                         GEMM_SMEM);

    // 0) split all GEMM operands to bf16 hi/lo
    presplit<<<dim3(256, 9), 256>>>(inQ, inK, inV, WQ1, WK1, WV1, WV2, Wfc1, Wfc2);
    // 1) projections: Q1, K1, V1, V2
    mma_gemm<<<dim3(32, 4, 4), 256, GEMM_SMEM>>>(inQ, 0);
    // 2) attention: S once, softmax + P output, O = E@V / l (bf16 split out)
    attn_mma<<<dim3(64, 32), 256, ATTN_SMEM>>>(Pout);
    // 3) FC + residual
    mma_gemm<<<dim3(32, 4, 2), 256, GEMM_SMEM>>>(inQ, 4);
    // 4) LayerNorm -> final output
    ln_kernel<<<dim3(B_ * S_ * 2), 256>>>(ln_g, ln_b, out);
}

// round 6
// speedup vs baseline: 2.2407x; 1.2710x over previous
#include <cuda_runtime.h>
#include <cuda_bf16.h>
#include <math.h>
#include <stdint.h>

// Problem constants
#define B_  4
#define S_  1024
#define D_  1024
#define H_  16
#define DKH_ 32
#define DV_  64

// ---------------------------------------------------------------------------
// Scratch (device globals; no allocations allowed)
// ---------------------------------------------------------------------------
__device__ __nv_bfloat16 pQh[4096*512],  pQl[4096*512];
__device__ __nv_bfloat16 pKh[4096*512],  pKl[4096*512];
__device__ __nv_bfloat16 pVh_[4096*1024], pVl_[4096*1024];
__device__ __nv_bfloat16 pWh[6*512*512], pWl[6*512*512];
__device__ __nv_bfloat16 g_Q1h[64*1024*32], g_Q1l[64*1024*32]; // pre-scaled
__device__ __nv_bfloat16 g_K1h[64*1024*32], g_K1l[64*1024*32];
__device__ __nv_bfloat16 g_Vh [64*1024*64], g_Vl [64*1024*64];
__device__ __nv_bfloat16 qkvh[4096*1024], qkvl[4096*1024];
__device__ float g_tmp[B_*S_*D_];

// ===========================================================================
// helpers
// ===========================================================================
__device__ __forceinline__ uint32_t smem_u32(const void* p) {
    uint32_t a;
    asm("{ .reg .u64 t; cvta.to.shared.u64 t, %1; cvt.u32.u64 %0, t; }"
        : "=r"(a) : "l"(p));
    return a;
}
__device__ __forceinline__ void ldsm_x4(uint32_t& r0, uint32_t& r1,
                                        uint32_t& r2, uint32_t& r3, uint32_t addr) {
    asm volatile("ldmatrix.sync.aligned.m8n8.x4.shared.b16 {%0,%1,%2,%3}, [%4];"
                 : "=r"(r0), "=r"(r1), "=r"(r2), "=r"(r3) : "r"(addr));
}
__device__ __forceinline__ void ldsm_x2(uint32_t& r0, uint32_t& r1, uint32_t addr) {
    asm volatile("ldmatrix.sync.aligned.m8n8.x2.shared.b16 {%0,%1}, [%2];"
                 : "=r"(r0), "=r"(r1) : "r"(addr));
}
__device__ __forceinline__ void ldsm_x2t(uint32_t& r0, uint32_t& r1, uint32_t addr) {
    asm volatile("ldmatrix.sync.aligned.m8n8.x2.trans.shared.b16 {%0,%1}, [%2];"
                 : "=r"(r0), "=r"(r1) : "r"(addr));
}
__device__ __forceinline__ void mma_bf16(float* c, uint32_t a0, uint32_t a1,
                                         uint32_t a2, uint32_t a3,
                                         uint32_t b0, uint32_t b1) {
    asm volatile("mma.sync.aligned.m16n8k16.row.col.f32.bf16.bf16.f32 "
                 "{%0,%1,%2,%3}, {%4,%5,%6,%7}, {%8,%9}, {%0,%1,%2,%3};"
                 : "+f"(c[0]), "+f"(c[1]), "+f"(c[2]), "+f"(c[3])
                 : "r"(a0), "r"(a1), "r"(a2), "r"(a3), "r"(b0), "r"(b1));
}
__device__ __forceinline__ uint32_t pack_bf16(__nv_bfloat16 a, __nv_bfloat16 b) {
    __nv_bfloat162 t; t.x = a; t.y = b;
    return *reinterpret_cast<uint32_t*>(&t);
}
__device__ __forceinline__ void split2(float x, float y, uint32_t& hi, uint32_t& lo) {
    __nv_bfloat16 hx = __float2bfloat16_rn(x);
    __nv_bfloat16 hy = __float2bfloat16_rn(y);
    __nv_bfloat16 lx = __float2bfloat16_rn(x - __bfloat162float(hx));
    __nv_bfloat16 ly = __float2bfloat16_rn(y - __bfloat162float(hy));
    hi = pack_bf16(hx, hy);
    lo = pack_bf16(lx, ly);
}
__device__ __forceinline__ void cp16(uint32_t dst, const void* src) {
    asm volatile("cp.async.cg.shared.global [%0], [%1], 16;"
                 :: "r"(dst), "l"(src));
}
#define CP_COMMIT()  asm volatile("cp.async.commit_group;" ::: "memory")
#define CP_WAIT(N)   asm volatile("cp.async.wait_group %0;" :: "n"(N) : "memory")

// ===========================================================================
// presplit: fp32 -> bf16 hi/lo for all GEMM operands.
// ===========================================================================
__global__ void __launch_bounds__(256)
presplit(const float* __restrict__ inQ, const float* __restrict__ inK,
         const float* __restrict__ inV,
         const float* __restrict__ W0, const float* __restrict__ W1,
         const float* __restrict__ W2, const float* __restrict__ W3,
         const float* __restrict__ W4, const float* __restrict__ W5)
{
    const int seg = blockIdx.y;
    const int gid = blockIdx.x * 256 + threadIdx.x;
    const int stride4 = gridDim.x * 256 * 4;

    if (seg < 2) {
        const float* s = seg ? inK : inQ;
        __nv_bfloat16* dh = seg ? pKh : pQh;
        __nv_bfloat16* dl = seg ? pKl : pQl;
        for (int i = gid * 4; i < 4096 * 512; i += stride4) {
            int row = i >> 9, col = i & 511;
            float4 v = *(const float4*)&s[(size_t)row * 1024 + col];
            uint32_t h0, l0, h1, l1;
            split2(v.x, v.y, h0, l0); split2(v.z, v.w, h1, l1);
            *(uint2*)&dh[i] = make_uint2(h0, h1);
            *(uint2*)&dl[i] = make_uint2(l0, l1);
        }
    } else if (seg == 2) {
        for (int i = gid * 4; i < 4096 * 1024; i += stride4) {
            float4 v = *(const float4*)&inV[i];
            uint32_t h0, l0, h1, l1;
            split2(v.x, v.y, h0, l0); split2(v.z, v.w, h1, l1);
            *(uint2*)&pVh_[i] = make_uint2(h0, h1);
            *(uint2*)&pVl_[i] = make_uint2(l0, l1);
        }
    } else {
        const int w = seg - 3;
        const float* s = (w == 0) ? W0 : (w == 1) ? W1 : (w == 2) ? W2
                       : (w == 3) ? W3 : (w == 4) ? W4 : W5;
        __nv_bfloat16* dh = pWh + (size_t)w * 262144;
        __nv_bfloat16* dl = pWl + (size_t)w * 262144;
        for (int i = gid * 4; i < 262144; i += stride4) {
            float4 v = *(const float4*)&s[i];
            uint32_t h0, l0, h1, l1;
            split2(v.x, v.y, h0, l0); split2(v.z, v.w, h1, l1);
            *(uint2*)&dh[i] = make_uint2(h0, h1);
            *(uint2*)&dl[i] = make_uint2(l0, l1);
        }
    }
}

// ===========================================================================
// HMMA GEMM, cp.async double-buffered (fill-after-sync, 1 sync/chunk).
// CTA tile 128x128, 8 warps, K chunk 32.
// ===========================================================================
#define APITCH 80
#define BPITCH 272
#define G_AH(buf) ((buf) * 10240u)
#define G_AL(buf) (20480u + (buf) * 10240u)
#define G_BH(buf) (40960u + (buf) * 8704u)
#define G_BL(buf) (58368u + (buf) * 8704u)
#define GEMM_SMEM 75776

__global__ void __launch_bounds__(256, 1)
mma_gemm(const float* __restrict__ inQ, int mode_base)
{
    extern __shared__ unsigned char sm[];
    const uint32_t smb = smem_u32(sm);

    const int mode = mode_base + blockIdx.z;
    const __nv_bfloat16 *pAh, *pAl;
    int apitch, aoff;
    switch (mode) {
        case 0: pAh = pQh;  pAl = pQl;  apitch = 512;  aoff = 0;   break;
        case 1: pAh = pKh;  pAl = pKl;  apitch = 512;  aoff = 0;   break;
        case 2: pAh = pVh_; pAl = pVl_; apitch = 1024; aoff = 0;   break;
        case 3: pAh = pVh_; pAl = pVl_; apitch = 1024; aoff = 512; break;
        case 4: pAh = qkvh; pAl = qkvl; apitch = 1024; aoff = 0;   break;
        default:pAh = qkvh; pAl = qkvl; apitch = 1024; aoff = 512; break;
    }
    const __nv_bfloat16* wh = pWh + (size_t)mode * 262144;
    const __nv_bfloat16* wl = pWl + (size_t)mode * 262144;

    const int m0 = blockIdx.x * 128;
    const int n0 = blockIdx.y * 128;
    const int tid  = threadIdx.x;
    const int wid  = tid >> 5;
    const int lane = tid & 31;
    const int wy = wid >> 2;
    const int wx = wid & 3;

    const int ar = tid >> 2, aseg = tid & 3;
    const int br = tid >> 4, bseg = tid & 15;

    #define GFILL(buf, k0)                                                        \
    {                                                                             \
        _Pragma("unroll")                                                         \
        for (int it = 0; it < 2; ++it) {                                          \
            int row = ar + it * 64;                                               \
            const __nv_bfloat16* sh = pAh + (size_t)(m0 + row) * apitch + aoff + (k0) + aseg * 8; \
            const __nv_bfloat16* sl = pAl + (size_t)(m0 + row) * apitch + aoff + (k0) + aseg * 8; \
            uint32_t d = (uint32_t)(row * APITCH + aseg * 16);                    \
            cp16(smb + G_AH(buf) + d, sh);                                        \
            cp16(smb + G_AL(buf) + d, sl);                                        \
        }                                                                         \
        _Pragma("unroll")                                                         \
        for (int it = 0; it < 2; ++it) {                                          \
            int row = br + it * 16;                                               \
            const __nv_bfloat16* sh = wh + (size_t)((k0) + row) * 512 + n0 + bseg * 8; \
            const __nv_bfloat16* sl = wl + (size_t)((k0) + row) * 512 + n0 + bseg * 8; \
            uint32_t d = (uint32_t)(row * BPITCH + bseg * 16);                    \
            cp16(smb + G_BH(buf) + d, sh);                                        \
            cp16(smb + G_BL(buf) + d, sl);                                        \
        }                                                                         \
        CP_COMMIT();                                                              \
    }

    float c[4][4][4] = {};

    const int a_row_in_tile = lane & 15;
    const int a_kseg        = (lane >> 4) & 1;
    const int b_krow        = (lane & 7) + ((lane >> 3) & 1) * 8;

    GFILL(0, 0);

    for (int chunk = 0; chunk < 16; ++chunk) {
        CP_WAIT(0);
        __syncthreads();
        if (chunk + 1 < 16) GFILL((chunk + 1) & 1, (chunk + 1) * 32);

        const uint32_t ahb = smb + G_AH(chunk & 1);
        const uint32_t alb = smb + G_AL(chunk & 1);
        const uint32_t bhb = smb + G_BH(chunk & 1);
        const uint32_t blb = smb + G_BL(chunk & 1);

        #pragma unroll
        for (int ks = 0; ks < 2; ++ks) {
            uint32_t ahf[4][4], alf[4][4];
            #pragma unroll
            for (int mt = 0; mt < 4; ++mt) {
                int row = wy * 64 + mt * 16 + a_row_in_tile;
                uint32_t aoffb = (uint32_t)(row * APITCH + ks * 32 + a_kseg * 16);
                ldsm_x4(ahf[mt][0], ahf[mt][1], ahf[mt][2], ahf[mt][3], ahb + aoffb);
                ldsm_x4(alf[mt][0], alf[mt][1], alf[mt][2], alf[mt][3], alb + aoffb);
            }
            uint32_t bhf[4][2], blf[4][2];
            #pragma unroll
            for (int nt = 0; nt < 4; ++nt) {
                uint32_t boffb = (uint32_t)((ks * 16 + b_krow) * BPITCH
                                            + (wx * 32 + nt * 8) * 2);
                ldsm_x2t(bhf[nt][0], bhf[nt][1], bhb + boffb);
                ldsm_x2t(blf[nt][0], blf[nt][1], blb + boffb);
            }
            #pragma unroll
            for (int mt = 0; mt < 4; ++mt) {
                #pragma unroll
                for (int nt = 0; nt < 4; ++nt) {
                    mma_bf16(c[mt][nt], ahf[mt][0], ahf[mt][1], ahf[mt][2], ahf[mt][3],
                             bhf[nt][0], bhf[nt][1]);
                    mma_bf16(c[mt][nt], ahf[mt][0], ahf[mt][1], ahf[mt][2], ahf[mt][3],
                             blf[nt][0], blf[nt][1]);
                    mma_bf16(c[mt][nt], alf[mt][0], alf[mt][1], alf[mt][2], alf[mt][3],
                             bhf[nt][0], bhf[nt][1]);
                }
            }
        }
    }

    // ---- epilogue ----
    const int gid = lane >> 2;
    const int tig = lane & 3;

    #pragma unroll
    for (int mt = 0; mt < 4; ++mt) {
        int row = m0 + wy * 64 + mt * 16 + gid;
        int b = row >> 10, s = row & 1023;
        #pragma unroll
        for (int nt = 0; nt < 4; ++nt) {
            int col = n0 + wx * 32 + nt * 8 + tig * 2;
            float2 v01 = make_float2(c[mt][nt][0], c[mt][nt][1]);
            float2 v23 = make_float2(c[mt][nt][2], c[mt][nt][3]);
            if (mode <= 1) {
                int h = col >> 5, d = col & 31;
                __nv_bfloat16* dh = (mode == 0) ? g_Q1h : g_K1h;
                __nv_bfloat16* dl = (mode == 0) ? g_Q1l : g_K1l;
                float sc = (mode == 0) ? 0.17677669529663688f : 1.0f;
                size_t base = ((size_t)(b * 16 + h) * 1024) * 32 + d;
                uint32_t hi, lo;
                split2(v01.x * sc, v01.y * sc, hi, lo);
                *(uint32_t*)&dh[base + (size_t)s * 32] = hi;
                *(uint32_t*)&dl[base + (size_t)s * 32] = lo;
                split2(v23.x * sc, v23.y * sc, hi, lo);
                *(uint32_t*)&dh[base + (size_t)(s + 8) * 32] = hi;
                *(uint32_t*)&dl[base + (size_t)(s + 8) * 32] = lo;
            } else if (mode <= 3) {
                int h = col >> 5, d = (col & 31) + (mode == 3 ? 32 : 0);
                size_t base = ((size_t)(b * 16 + h) * 1024) * 64 + d;
                uint32_t hi, lo;
                split2(v01.x, v01.y, hi, lo);
                *(uint32_t*)&g_Vh[base + (size_t)s * 64] = hi;
                *(uint32_t*)&g_Vl[base + (size_t)s * 64] = lo;
                split2(v23.x, v23.y, hi, lo);
                *(uint32_t*)&g_Vh[base + (size_t)(s + 8) * 64] = hi;
                *(uint32_t*)&g_Vl[base + (size_t)(s + 8) * 64] = lo;
            } else {
                int half = mode - 4;
                size_t idx0 = (size_t)row * 1024 + half * 512 + col;
                size_t idx1 = idx0 + 8 * 1024;
                float2 r0 = *(const float2*)&inQ[idx0];
                float2 r1 = *(const float2*)&inQ[idx1];
                *(float2*)&g_tmp[idx0] = make_float2(v01.x + r0.x, v01.y + r0.y);
                *(float2*)&g_tmp[idx1] = make_float2(v23.x + r1.x, v23.y + r1.y);
            }
        }
    }
    #undef GFILL
}

// ===========================================================================
// Flash attention, 2-pass, register-reuse PV. CTA = (bh, 64-row q-slab),
// 128 threads (4 warps x 16 q-rows). 3 CTAs/SM.
// ===========================================================================
#define AT_K_H(buf) ((buf) * 5120u)
#define AT_K_L(buf) (10240u + (buf) * 5120u)
#define AT_V_H(buf) (20480u + (buf) * 9216u)
#define AT_V_L(buf) (38912u + (buf) * 9216u)
#define AT_Q_H 20480u            /* overlay on V region (V unused until pass 2) */
#define AT_Q_L 25600u
#define ATTN_SMEM 57344

__global__ void __launch_bounds__(128, 3)
attn_flash(float* __restrict__ Pout)
{
    extern __shared__ unsigned char sm[];
    const uint32_t smb = smem_u32(sm);

    const int bh = blockIdx.x;
    const int qs = 15 - (int)blockIdx.y;   // LPT: heavy slabs first
    const int q0 = qs * 64;
    const int nkt = qs + 1;
    const int ncol = nkt * 64;
    const int tid = threadIdx.x, wid = tid >> 5, lane = tid & 31;

    const int frow = tid >> 1;
    const int fs2  = (tid & 1) * 2;
    const int fs4  = (tid & 1) * 4;

#define KFILL(buf, kt)                                                            \
    {                                                                             \
        const __nv_bfloat16* sh_ = g_K1h + ((size_t)bh*1024 + (size_t)(kt)*64 + frow)*32 + fs2*8; \
        const __nv_bfloat16* sl_ = g_K1l + ((size_t)bh*1024 + (size_t)(kt)*64 + frow)*32 + fs2*8; \
        uint32_t d_ = (uint32_t)(frow * 80 + fs2 * 16);                           \
        cp16(smb + AT_K_H(buf) + d_,      sh_);                                   \
        cp16(smb + AT_K_H(buf) + d_ + 16, sh_ + 8);                               \
        cp16(smb + AT_K_L(buf) + d_,      sl_);                                   \
        cp16(smb + AT_K_L(buf) + d_ + 16, sl_ + 8);                               \
    }
#define VFILL(buf, kt)                                                            \
    {                                                                             \
        const __nv_bfloat16* sh_ = g_Vh + ((size_t)bh*1024 + (size_t)(kt)*64 + frow)*64 + fs4*8; \
        const __nv_bfloat16* sl_ = g_Vl + ((size_t)bh*1024 + (size_t)(kt)*64 + frow)*64 + fs4*8; \
        uint32_t d_ = (uint32_t)(frow * 144 + fs4 * 16);                          \
        _Pragma("unroll")                                                         \
        for (int u_ = 0; u_ < 4; ++u_) {                                          \
            cp16(smb + AT_V_H(buf) + d_ + u_*16, sh_ + u_*8);                     \
            cp16(smb + AT_V_L(buf) + d_ + u_*16, sl_ + u_*8);                     \
        }                                                                         \
    }

    // prefetch K tile 0 for pass 1
    KFILL(0, 0); CP_COMMIT();

    // stage Q slab (64 x 32 bf16 hi/lo) and build fragments
    {
        const __nv_bfloat16* qh = g_Q1h + ((size_t)bh*1024 + q0 + frow)*32 + fs2*8;
        const __nv_bfloat16* ql = g_Q1l + ((size_t)bh*1024 + q0 + frow)*32 + fs2*8;
        uint32_t d = (uint32_t)(frow * 80 + fs2 * 16);
        *(uint4*)(sm + AT_Q_H + d)      = *(const uint4*)qh;
        *(uint4*)(sm + AT_Q_H + d + 16) = *(const uint4*)(qh + 8);
        *(uint4*)(sm + AT_Q_L + d)      = *(const uint4*)ql;
        *(uint4*)(sm + AT_Q_L + d + 16) = *(const uint4*)(ql + 8);
    }
    __syncthreads();

    uint32_t qfh[2][4], qfl[2][4];
    #pragma unroll
    for (int ks = 0; ks < 2; ++ks) {
        uint32_t off = (uint32_t)((wid * 16 + (lane & 15)) * 80
                                  + ks * 32 + ((lane >> 4) & 1) * 16);
        ldsm_x4(qfh[ks][0], qfh[ks][1], qfh[ks][2], qfh[ks][3], smb + AT_Q_H + off);
        ldsm_x4(qfl[ks][0], qfl[ks][1], qfl[ks][2], qfl[ks][3], smb + AT_Q_L + off);
    }

    const int gr0 = q0 + wid * 16 + (lane >> 2);   // thread row 0 (row 1 = +8)

    // S compute macro: fills s[8][4] from buf
    #define SCOMP(buf)                                                            \
    {                                                                             \
        const uint32_t khb = smb + AT_K_H(buf);                                   \
        const uint32_t klb = smb + AT_K_L(buf);                                   \
        _Pragma("unroll")                                                         \
        for (int ks = 0; ks < 2; ++ks) {                                          \
            _Pragma("unroll")                                                     \
            for (int nt = 0; nt < 8; ++nt) {                                      \
                uint32_t boff = (uint32_t)((nt * 8 + (lane & 7)) * 80             \
                                           + ks * 32 + ((lane >> 3) & 1) * 16);   \
                uint32_t b0, b1, d0, d1;                                          \
                ldsm_x2(b0, b1, khb + boff);                                      \
                ldsm_x2(d0, d1, klb + boff);                                      \
                mma_bf16(s[nt], qfh[ks][0], qfh[ks][1], qfh[ks][2], qfh[ks][3], b0, b1); \
                mma_bf16(s[nt], qfh[ks][0], qfh[ks][1], qfh[ks][2], qfh[ks][3], d0, d1); \
                mma_bf16(s[nt], qfl[ks][0], qfl[ks][1], qfl[ks][2], qfl[ks][3], b0, b1); \
            }                                                                     \
        }                                                                         \
    }
    #define SMASK(kt)                                                             \
    if ((kt) == nkt - 1) {                                                        \
        int cb = (kt) * 64 + (lane & 3) * 2;                                      \
        _Pragma("unroll")                                                         \
        for (int nt = 0; nt < 8; ++nt) {                                          \
            int c0 = cb + nt * 8;                                                 \
            if (c0     > gr0)     s[nt][0] = -1e30f;                              \
            if (c0 + 1 > gr0)     s[nt][1] = -1e30f;                              \
            if (c0     > gr0 + 8) s[nt][2] = -1e30f;                              \
            if (c0 + 1 > gr0 + 8) s[nt][3] = -1e30f;                              \
        }                                                                         \
    }

    // ================= Pass 1: (m, l) =================
    float m0 = -1e30f, m1 = -1e30f, l0 = 0.f, l1 = 0.f;

    for (int kt = 0; kt < nkt; ++kt) {
        CP_WAIT(0);
        __syncthreads();
        if (kt + 1 < nkt) { KFILL((kt + 1) & 1, kt + 1); CP_COMMIT(); }

        float s[8][4] = {};
        SCOMP(kt & 1);
        SMASK(kt);

        float tm0 = -1e30f, tm1 = -1e30f;
        #pragma unroll
        for (int nt = 0; nt < 8; ++nt) {
            tm0 = fmaxf(tm0, fmaxf(s[nt][0], s[nt][1]));
            tm1 = fmaxf(tm1, fmaxf(s[nt][2], s[nt][3]));
        }
        tm0 = fmaxf(tm0, __shfl_xor_sync(0xffffffffu, tm0, 1));
        tm0 = fmaxf(tm0, __shfl_xor_sync(0xffffffffu, tm0, 2));
        tm1 = fmaxf(tm1, __shfl_xor_sync(0xffffffffu, tm1, 1));
        tm1 = fmaxf(tm1, __shfl_xor_sync(0xffffffffu, tm1, 2));
        float nm0 = fmaxf(m0, tm0), nm1 = fmaxf(m1, tm1);
        float a0 = 0.f, a1 = 0.f;
        #pragma unroll
        for (int nt = 0; nt < 8; ++nt) {
            a0 += __expf(s[nt][0] - nm0) + __expf(s[nt][1] - nm0);
            a1 += __expf(s[nt][2] - nm1) + __expf(s[nt][3] - nm1);
        }
        a0 += __shfl_xor_sync(0xffffffffu, a0, 1);
        a0 += __shfl_xor_sync(0xffffffffu, a0, 2);
        a1 += __shfl_xor_sync(0xffffffffu, a1, 1);
        a1 += __shfl_xor_sync(0xffffffffu, a1, 2);
        l0 = l0 * __expf(m0 - nm0) + a0;  m0 = nm0;
        l1 = l1 * __expf(m1 - nm1) + a1;  m1 = nm1;
    }
    const float li0 = 1.0f / l0, li1 = 1.0f / l1;

    // ================= Pass 2: P write + O = P @ V =================
    __syncthreads();                       // pass-1 reads done before refill
    KFILL(0, 0); VFILL(0, 0); CP_COMMIT();

    float o[8][4] = {};

    for (int kt = 0; kt < nkt; ++kt) {
        CP_WAIT(0);
        __syncthreads();
        if (kt + 1 < nkt) {
            KFILL((kt + 1) & 1, kt + 1);
            VFILL((kt + 1) & 1, kt + 1);
            CP_COMMIT();
        }

        float s[8][4] = {};
        SCOMP(kt & 1);
        SMASK(kt);

        // p = exp(s - m) * linv  (masked -> exactly 0)
        #pragma unroll
        for (int nt = 0; nt < 8; ++nt) {
            s[nt][0] = __expf(s[nt][0] - m0) * li0;
            s[nt][1] = __expf(s[nt][1] - m0) * li0;
            s[nt][2] = __expf(s[nt][2] - m1) * li1;
            s[nt][3] = __expf(s[nt][3] - m1) * li1;
        }

        // write P from registers
        {
            float* pr0 = Pout + ((size_t)bh * 1024 + gr0) * 1024 + kt * 64 + (lane & 3) * 2;
            float* pr1 = pr0 + 8 * 1024;
            #pragma unroll
            for (int nt = 0; nt < 8; ++nt) {
                *(float2*)&pr0[nt * 8] = make_float2(s[nt][0], s[nt][1]);
                *(float2*)&pr1[nt * 8] = make_float2(s[nt][2], s[nt][3]);
            }
        }

        // PV via register-reuse (C-frag == A-frag layout)
        const uint32_t vhb = smb + AT_V_H(kt & 1);
        const uint32_t vlb = smb + AT_V_L(kt & 1);
        #pragma unroll
        for (int ksv = 0; ksv < 4; ++ksv) {
            uint32_t ah[4], al[4];
            split2(s[2*ksv][0],   s[2*ksv][1],   ah[0], al[0]);
            split2(s[2*ksv][2],   s[2*ksv][3],   ah[1], al[1]);
            split2(s[2*ksv+1][0], s[2*ksv+1][1], ah[2], al[2]);
            split2(s[2*ksv+1][2], s[2*ksv+1][3], ah[3], al[3]);
            uint32_t vrow = (uint32_t)((ksv * 16 + (lane & 15)) * 144);
            #pragma unroll
            for (int ntv = 0; ntv < 8; ++ntv) {
                uint32_t vb0, vb1, wb0, wb1;
                ldsm_x2t(vb0, vb1, vhb + vrow + ntv * 16);
                ldsm_x2t(wb0, wb1, vlb + vrow + ntv * 16);
                mma_bf16(o[ntv], ah[0], ah[1], ah[2], ah[3], vb0, vb1);
                mma_bf16(o[ntv], ah[0], ah[1], ah[2], ah[3], wb0, wb1);
                mma_bf16(o[ntv], al[0], al[1], al[2], al[3], vb0, vb1);
            }
        }
    }

    // zero-fill P tail (cols >= ncol)
    {
        float4 z = make_float4(0.f, 0.f, 0.f, 0.f);
        float* base0 = Pout + ((size_t)bh * 1024 + gr0) * 1024;
        float* base1 = base0 + 8 * 1024;
        for (int col = ncol + (lane & 3) * 4; col < 1024; col += 16) {
            *(float4*)&base0[col] = z;
            *(float4*)&base1[col] = z;
        }
    }

    // O epilogue -> qkvh/qkvl (bf16 split); p already includes 1/l
    {
        const int b = bh >> 4, h = bh & 15;
        size_t i0 = ((size_t)(b * 1024 + gr0)) * 1024 + h * 64 + (lane & 3) * 2;
        size_t i1 = i0 + 8 * 1024;
        #pragma unroll
        for (int ntv = 0; ntv < 8; ++ntv) {
            uint32_t hi, lo;
            split2(o[ntv][0], o[ntv][1], hi, lo);
            *(uint32_t*)&qkvh[i0 + ntv * 8] = hi;
            *(uint32_t*)&qkvl[i0 + ntv * 8] = lo;
            split2(o[ntv][2], o[ntv][3], hi, lo);
            *(uint32_t*)&qkvh[i1 + ntv * 8] = hi;
            *(uint32_t*)&qkvl[i1 + ntv * 8] = lo;
        }
    }
    #undef KFILL
    #undef VFILL
    #undef SCOMP
    #undef SMASK
}

// ---------------------------------------------------------------------------
// LayerNorm (unchanged)
// ---------------------------------------------------------------------------
__global__ void ln_kernel(const float* __restrict__ gamma,
                          const float* __restrict__ beta,
                          float* __restrict__ out)
{
    const int row = blockIdx.x >> 1;
    const int half = blockIdx.x & 1;
    const float* x = g_tmp + (size_t)row * 1024 + half * 512;
    const int tid = threadIdx.x;

    float v0 = x[tid], v1 = x[tid + 256];
    float s = v0 + v1;
    float sq = v0 * v0 + v1 * v1;
    #pragma unroll
    for (int off = 16; off > 0; off >>= 1) {
        s  += __shfl_xor_sync(0xffffffffu, s,  off);
        sq += __shfl_xor_sync(0xffffffffu, sq, off);
    }
    __shared__ float ss[8], sqq[8];
    if ((tid & 31) == 0) { ss[tid >> 5] = s; sqq[tid >> 5] = sq; }
    __syncthreads();
    float tot = 0.f, totq = 0.f;
    #pragma unroll
    for (int w = 0; w < 8; w++) { tot += ss[w]; totq += sqq[w]; }

    float mu = tot * (1.0f / 512.0f);
    float var = totq * (1.0f / 512.0f) - mu * mu;
    float rstd = rsqrtf(var + 1e-5f);

    size_t obase = (size_t)row * 1024 + half * 512;
    out[obase + tid]       = (v0 - mu) * rstd * gamma[tid]       + beta[tid];
    out[obase + tid + 256] = (v1 - mu) * rstd * gamma[tid + 256] + beta[tid + 256];
}

// ---------------------------------------------------------------------------
extern "C" void kernel_launch(void* const* d_in, const int* in_sizes, int n_in,
                              void* d_out, int out_size)
{
    const float* inQ  = (const float*)d_in[0];
    const float* inK  = (const float*)d_in[1];
    const float* inV  = (const float*)d_in[2];
    const float* WQ1  = (const float*)d_in[4];
    const float* WK1  = (const float*)d_in[5];
    const float* WV1  = (const float*)d_in[6];
    const float* WV2  = (const float*)d_in[9];
    const float* Wfc1 = (const float*)d_in[10];
    const float* Wfc2 = (const float*)d_in[11];
    const float* ln_g = (const float*)d_in[12];
    const float* ln_b = (const float*)d_in[13];

    float* out  = (float*)d_out;
    float* Pout = out + (size_t)B_ * S_ * D_;

    cudaFuncSetAttribute(attn_flash, cudaFuncAttributeMaxDynamicSharedMemorySize,
                         ATTN_SMEM);
    cudaFuncSetAttribute(mma_gemm, cudaFuncAttributeMaxDynamicSharedMemorySize,
                         GEMM_SMEM);

    // 0) split all GEMM operands to bf16 hi/lo
    presplit<<<dim3(256, 9), 256>>>(inQ, inK, inV, WQ1, WK1, WV1, WV2, Wfc1, Wfc2);
    // 1) projections: Q1, K1, V1, V2
    mma_gemm<<<dim3(32, 4, 4), 256, GEMM_SMEM>>>(inQ, 0);
    // 2) flash attention: P output + O (bf16 split out)
    attn_flash<<<dim3(64, 16), 128, ATTN_SMEM>>>(Pout);
    // 3) FC + residual
    mma_gemm<<<dim3(32, 4, 2), 256, GEMM_SMEM>>>(inQ, 4);
    // 4) LayerNorm -> final output
    ln_kernel<<<dim3(B_ * S_ * 2), 256>>>(ln_g, ln_b, out);
}